// round 3
// baseline (speedup 1.0000x reference)
#include <cuda_runtime.h>
#include <math.h>
#include <stddef.h>

// Problem dims
// B=64, C=64, CO=64, N=400, L=24, K=3, KT=3
// x layout [b,c,n,l]: idx = ((b*64+c)*400+n)*24+l
#define SZ_X      39321600   // 64*64*400*24
#define SZ_S      10240000   // 64*400*400
#define SZ_T      36864      // 64*24*24
#define OFF_S     39321600
#define OFF_T     49561600
#define SZ_TOTAL  49598464

// ---------------- scratch (device globals; allocation-free) ----------------
__device__ float g_xin[SZ_X];            // x_input [b,o,n,l]
__device__ float g_xta[SZ_X];            // x_TAt   [b,n,c,l]  (n-major for SGEMM B operand)
__device__ float g_Y[64*2*400*64*24];    // cheby outputs k=1,2 only: [b,k-1,q,c,l]
__device__ float g_sg[SZ_X];             // spatial_gcn (relu) [b,o,n,l]
__device__ float g_f1t[64*24*400];       // [b,l,n]
__device__ float g_f2t[64*64*24];        // [b,c,l]
__device__ float g_f1s[64*400*24];       // [b,n,l]
__device__ float g_f2s[64*64*400];       // [b,c,n]
__device__ float g_gs[64*400*64];        // [b,n,c]
__device__ float g_lsig[64*400*400];     // sigmoid logits [b,q,n]
__device__ float g_lg2s[64*400*400];     // s_v @ lsig [b,p,n]
__device__ float g_Sscr[SZ_S];           // S_coef [b,p,n]
__device__ float g_T[64*24*24];          // T [b,p,l]
__device__ float g_adj2[400*400];
__device__ float g_cmaxs[64*400];
__device__ float g_psum[64*400];
__device__ float g_psq[64*400];
__device__ float g_mu[64];
__device__ float g_rstd[64];

// ---------------- conv1: x_input[b,o,n,l] = conv1_w[o,:]·x[b,:,n,l] + b ----------------
__global__ __launch_bounds__(128) void conv1_kernel(const float* __restrict__ x,
                                                    const float* __restrict__ w,
                                                    const float* __restrict__ bias) {
    int n = blockIdx.x, b = blockIdx.y;
    __shared__ float xs[64 * 24];
    __shared__ float ws[64 * 64];
    int tid = threadIdx.x;
    const float* xb = x + (size_t)b * 614400;
    for (int i = tid; i < 1536; i += 128) {
        int c = i / 24, l = i % 24;
        xs[i] = xb[c * 9600 + n * 24 + l];
    }
    for (int i = tid; i < 4096; i += 128) ws[i] = w[i];
    __syncthreads();
    int o  = (tid >> 2) * 2;
    int lg = (tid & 3) * 6;
    float acc0[6], acc1[6];
    float b0 = bias[o], b1 = bias[o + 1];
#pragma unroll
    for (int j = 0; j < 6; j++) { acc0[j] = b0; acc1[j] = b1; }
    for (int c = 0; c < 64; c++) {
        float w0 = ws[o * 64 + c], w1 = ws[(o + 1) * 64 + c];
#pragma unroll
        for (int j = 0; j < 6; j++) {
            float xv = xs[c * 24 + lg + j];
            acc0[j] += w0 * xv;
            acc1[j] += w1 * xv;
        }
    }
    float* out = g_xin + (size_t)b * 614400 + n * 24;
#pragma unroll
    for (int j = 0; j < 6; j++) {
        out[o * 9600 + lg + j]       = acc0[j];
        out[(o + 1) * 9600 + lg + j] = acc1[j];
    }
}

// ---------------- fused per-(b,n) features: f1t, f1s, f2s ----------------
__global__ __launch_bounds__(256) void featA_kernel(const float* __restrict__ x,
                                                    const float* __restrict__ tcw1,
                                                    const float* __restrict__ scw1,
                                                    const float* __restrict__ scw2) {
    int n = blockIdx.x, b = blockIdx.y;
    __shared__ float xs[1536];
    __shared__ float c1[64], c2[64], c3[24];
    int tid = threadIdx.x;
    const float* xb = x + (size_t)b * 614400;
    for (int i = tid; i < 1536; i += 256) {
        int c = i / 24, l = i % 24;
        xs[i] = xb[c * 9600 + n * 24 + l];
    }
    if (tid < 64) c1[tid] = tcw1[tid];
    else if (tid < 128) c2[tid - 64] = scw1[tid - 64];
    else if (tid < 152) c3[tid - 128] = scw2[tid - 128];
    __syncthreads();
    if (tid < 24) {
        int l = tid;
        float a1 = 0.f, a2 = 0.f;
        for (int c = 0; c < 64; c++) {
            float xv = xs[c * 24 + l];
            a1 += c1[c] * xv;
            a2 += c2[c] * xv;
        }
        g_f1t[(b * 24 + l) * 400 + n] = a1;
        g_f1s[(b * 400 + n) * 24 + l] = a2;
    } else if (tid >= 64 && tid < 128) {
        int c = tid - 64;
        float a = 0.f;
        for (int l = 0; l < 24; l++) a += c3[l] * xs[c * 24 + l];
        g_f2s[(b * 64 + c) * 400 + n] = a;
    }
}

// ---------------- f2t[b,c,l] = sum_n t_cw2[n]*x[b,c,n,l] ----------------
__global__ __launch_bounds__(192) void f2t_kernel(const float* __restrict__ x,
                                                  const float* __restrict__ tcw2) {
    int c = blockIdx.x, b = blockIdx.y;
    __shared__ float red[192];
    int tid = threadIdx.x;
    int l = tid % 24, g = tid / 24;
    const float* xb = x + (size_t)b * 614400 + c * 9600;
    float a = 0.f;
    for (int n = g; n < 400; n += 8) a += tcw2[n] * xb[n * 24 + l];
    red[tid] = a;
    __syncthreads();
    if (tid < 24) {
        float s = 0.f;
        for (int gg = 0; gg < 8; gg++) s += red[gg * 24 + tid];
        g_f2t[(b * 64 + c) * 24 + tid] = s;
    }
}

// ---------------- temporal attention (per-batch block) ----------------
__global__ __launch_bounds__(256) void tatt_kernel(const float* __restrict__ tw,
                                                   const float* __restrict__ tb,
                                                   const float* __restrict__ tv) {
    int b = blockIdx.x;
    __shared__ float f1tile[24 * 64], twtile[64 * 64], f2ts[64 * 24], gt[24 * 64];
    __shared__ float lg[576], lg2[576], cmax[24], rsum[24];
    int tid = threadIdx.x;
    for (int i = tid; i < 1536; i += 256) f2ts[i] = g_f2t[b * 1536 + i];

    int pg = tid >> 6;       // 0..3 -> handles p = pg*6 .. pg*6+5
    int c  = tid & 63;
    float acc[6] = {0.f, 0.f, 0.f, 0.f, 0.f, 0.f};
    for (int n0 = 0; n0 < 400; n0 += 64) {
        __syncthreads();
        for (int i = tid; i < 1536; i += 256) {
            int p = i >> 6, nn = i & 63;
            f1tile[i] = (n0 + nn < 400) ? g_f1t[(b * 24 + p) * 400 + n0 + nn] : 0.f;
        }
        for (int i = tid; i < 4096; i += 256) {
            int nn = i >> 6, cc = i & 63;
            twtile[i] = (n0 + nn < 400) ? tw[(n0 + nn) * 64 + cc] : 0.f;
        }
        __syncthreads();
        for (int nn = 0; nn < 64; nn++) {
            float wv = twtile[nn * 64 + c];
#pragma unroll
            for (int j = 0; j < 6; j++) acc[j] += f1tile[(pg * 6 + j) * 64 + nn] * wv;
        }
    }
    __syncthreads();
#pragma unroll
    for (int j = 0; j < 6; j++) gt[(pg * 6 + j) * 64 + c] = acc[j];
    __syncthreads();
    // lg[p][l] = sigmoid(sum_c gt[p][c]*f2t[c][l] + t_b[p][l])
    for (int i = tid; i < 576; i += 256) {
        int p = i / 24, l = i % 24;
        float s = tb[i];
        for (int cc = 0; cc < 64; cc++) s += gt[p * 64 + cc] * f2ts[cc * 24 + l];
        lg[i] = 1.f / (1.f + expf(-s));
    }
    __syncthreads();
    // lg2[p][l] = sum_q tv[p][q]*lg[q][l]
    for (int i = tid; i < 576; i += 256) {
        int p = i / 24, l = i % 24;
        float s = 0.f;
        for (int q = 0; q < 24; q++) s += tv[p * 24 + q] * lg[q * 24 + l];
        lg2[i] = s;
    }
    __syncthreads();
    if (tid < 24) {
        float m = -1e30f;
        for (int p = 0; p < 24; p++) m = fmaxf(m, lg2[p * 24 + tid]);
        cmax[tid] = m;
    }
    __syncthreads();
    for (int i = tid; i < 576; i += 256) {
        int l = i % 24;
        lg[i] = expf(lg2[i] - cmax[l]);
    }
    __syncthreads();
    if (tid < 24) {
        float s = 0.f;
        for (int l = 0; l < 24; l++) s += lg[tid * 24 + l];
        rsum[tid] = s;
    }
    __syncthreads();
    for (int i = tid; i < 576; i += 256) {
        int p = i / 24;
        g_T[b * 576 + i] = lg[i] / rsum[p];
    }
}

// ---------------- x_TAt[b,n,c,q] = sum_l x[b,c,n,l]*T[b,q,l] ----------------
__global__ __launch_bounds__(64) void xta_kernel(const float* __restrict__ x) {
    int n = blockIdx.x, b = blockIdx.y;
    __shared__ float xs[1536], Ts[576];
    int tid = threadIdx.x;
    const float* xb = x + (size_t)b * 614400;
    for (int i = tid; i < 1536; i += 64) {
        int c = i / 24, l = i % 24;
        xs[i] = xb[c * 9600 + n * 24 + l];
    }
    for (int i = tid; i < 576; i += 64) Ts[i] = g_T[b * 576 + i];
    __syncthreads();
    int cg = (tid >> 2) * 4, qg = (tid & 3) * 6;
    float acc[4][6] = {};
    for (int l = 0; l < 24; l++) {
        float tvv[6];
#pragma unroll
        for (int j = 0; j < 6; j++) tvv[j] = Ts[(qg + j) * 24 + l];
#pragma unroll
        for (int i = 0; i < 4; i++) {
            float xv = xs[(cg + i) * 24 + l];
#pragma unroll
            for (int j = 0; j < 6; j++) acc[i][j] += xv * tvv[j];
        }
    }
    float* o = g_xta + ((size_t)(b * 400 + n)) * 1536;
#pragma unroll
    for (int i = 0; i < 4; i++)
#pragma unroll
        for (int j = 0; j < 6; j++) o[(cg + i) * 24 + qg + j] = acc[i][j];
}

// ---------------- gs[b,n,c] = sum_l f1s[b,n,l]*s_w[l,c] ----------------
__global__ __launch_bounds__(64) void gs_kernel(const float* __restrict__ sw) {
    int n = blockIdx.x, b = blockIdx.y;
    __shared__ float sws[24 * 64], f1row[24];
    int tid = threadIdx.x;
    for (int i = tid; i < 1536; i += 64) sws[i] = sw[i];
    if (tid < 24) f1row[tid] = g_f1s[(b * 400 + n) * 24 + tid];
    __syncthreads();
    float a = 0.f;
    for (int l = 0; l < 24; l++) a += f1row[l] * sws[l * 64 + tid];
    g_gs[(b * 400 + n) * 64 + tid] = a;
}

// ---------------- generic 64x64-tile SGEMM ----------------
// MODE 0: g_adj2 = A @ A            (A = supports)
// MODE 1: g_lsig = sigmoid(gs[b] @ f2s[b] + s_b)
// MODE 2: g_lg2s = s_v @ lsig[b]
template <int MODE>
__global__ __launch_bounds__(256) void tile64_kernel(const float* __restrict__ Aext,
                                                     const float* __restrict__ biasext,
                                                     int M, int N, int Kd) {
    int zb = blockIdx.z;
    const float* A;
    const float* Bm;
    float* C;
    if (MODE == 0) { A = Aext; Bm = Aext; C = g_adj2; }
    else if (MODE == 1) { A = g_gs + (size_t)zb * 25600; Bm = g_f2s + (size_t)zb * 25600; C = g_lsig + (size_t)zb * 160000; }
    else { A = Aext; Bm = g_lsig + (size_t)zb * 160000; C = g_lg2s + (size_t)zb * 160000; }

    int m0 = blockIdx.y * 64, n0 = blockIdx.x * 64;
    __shared__ float As[16][68], Bs[16][68];
    int tid = threadIdx.x;
    int tx = tid & 15, ty = tid >> 4;
    float acc[4][4] = {};
    for (int k0 = 0; k0 < Kd; k0 += 16) {
#pragma unroll
        for (int r = 0; r < 4; r++) {
            int lin = tid + 256 * r;
            int kk = lin & 15, m = lin >> 4;
            float v = 0.f;
            if (m0 + m < M && k0 + kk < Kd) v = A[(size_t)(m0 + m) * Kd + k0 + kk];
            As[kk][m] = v;
            int j = lin & 63, kk2 = lin >> 6;
            float v2 = 0.f;
            if (k0 + kk2 < Kd && n0 + j < N) v2 = Bm[(size_t)(k0 + kk2) * N + n0 + j];
            Bs[kk2][j] = v2;
        }
        __syncthreads();
#pragma unroll
        for (int kk = 0; kk < 16; kk++) {
            float a[4], bb[4];
#pragma unroll
            for (int i = 0; i < 4; i++) a[i] = As[kk][ty * 4 + i];
#pragma unroll
            for (int j = 0; j < 4; j++) bb[j] = Bs[kk][tx * 4 + j];
#pragma unroll
            for (int i = 0; i < 4; i++)
#pragma unroll
                for (int j = 0; j < 4; j++) acc[i][j] += a[i] * bb[j];
        }
        __syncthreads();
    }
#pragma unroll
    for (int i = 0; i < 4; i++) {
        int m = m0 + ty * 4 + i;
        if (m >= M) break;
#pragma unroll
        for (int j = 0; j < 4; j++) {
            int nn = n0 + tx * 4 + j;
            if (nn >= N) continue;
            float v = acc[i][j];
            if (MODE == 1) v = 1.f / (1.f + expf(-(v + biasext[(size_t)m * N + nn])));
            C[(size_t)m * N + nn] = v;
        }
    }
}

// ---------------- column max over p, then row softmax -> S ----------------
__global__ __launch_bounds__(512) void colmax_kernel() {
    int b = blockIdx.x;
    int tid = threadIdx.x;
    if (tid < 400) {
        const float* base = g_lg2s + (size_t)b * 160000 + tid;
        float m = -1e30f;
        for (int p = 0; p < 400; p++) m = fmaxf(m, base[p * 400]);
        g_cmaxs[b * 400 + tid] = m;
    }
}

__global__ __launch_bounds__(256) void smax_kernel() {
    int p = blockIdx.x, b = blockIdx.y;
    int tid = threadIdx.x;
    __shared__ float red[256];
    const float* row = g_lg2s + (size_t)b * 160000 + p * 400;
    const float* cm = g_cmaxs + b * 400;
    float* orow = g_Sscr + (size_t)b * 160000 + p * 400;
    float s = 0.f;
    for (int n = tid; n < 400; n += 256) {
        float e = expf(row[n] - cm[n]);
        orow[n] = e;
        s += e;
    }
    red[tid] = s;
    __syncthreads();
    for (int st = 128; st > 0; st >>= 1) {
        if (tid < st) red[tid] += red[tid + st];
        __syncthreads();
    }
    float inv = 1.f / red[0];
    for (int n = tid; n < 400; n += 256) orow[n] *= inv;
}

// ---------------- cheby k=1,2: Y[b,k-1] = (S .* Wk) @ xta[b]  (400x400 @ 400x1536) ---------
__global__ __launch_bounds__(256) void cheby_kernel(const float* __restrict__ adj) {
    int z = blockIdx.z;
    int b = z >> 1;
    int k = (z & 1) + 1;
    int q0 = blockIdx.y * 128;
    int j0 = blockIdx.x * 128;
    __shared__ float As[16][132];
    __shared__ float Bs[16][132];
    const float* Sb = g_Sscr + (size_t)b * 160000;
    const float* Xb = g_xta + (size_t)b * 614400;
    float acc[8][8] = {};
    int tid = threadIdx.x;
    int tx = tid & 15, ty = tid >> 4;
    for (int n0 = 0; n0 < 400; n0 += 16) {
#pragma unroll
        for (int r = 0; r < 8; r++) {
            int lin = tid + 256 * r;
            int kk = lin & 15, q = lin >> 4;
            int gq = q0 + q, gn = n0 + kk;
            float v = 0.f;
            if (gq < 400) {
                float s = Sb[gq * 400 + gn];
                float w;
                if (k == 1) w = adj[gq * 400 + gn];
                else w = 2.f * g_adj2[gq * 400 + gn] - (gq == gn ? 1.f : 0.f);
                v = s * w;
            }
            As[kk][q] = v;
        }
#pragma unroll
        for (int r = 0; r < 8; r++) {
            int lin = tid + 256 * r;
            int j = lin & 127, kk = lin >> 7;
            Bs[kk][j] = Xb[(size_t)(n0 + kk) * 1536 + j0 + j];
        }
        __syncthreads();
#pragma unroll
        for (int kk = 0; kk < 16; kk++) {
            float a[8], bb[8];
#pragma unroll
            for (int i = 0; i < 8; i++) a[i] = As[kk][ty * 8 + i];
#pragma unroll
            for (int j = 0; j < 8; j++) bb[j] = Bs[kk][tx * 8 + j];
#pragma unroll
            for (int i = 0; i < 8; i++)
#pragma unroll
                for (int j = 0; j < 8; j++) acc[i][j] += a[i] * bb[j];
        }
        __syncthreads();
    }
    float* Yb = g_Y + (size_t)(b * 2 + (k - 1)) * 614400;
#pragma unroll
    for (int i = 0; i < 8; i++) {
        int gq = q0 + ty * 8 + i;
        if (gq >= 400) break;
#pragma unroll
        for (int j = 0; j < 8; j++) Yb[(size_t)gq * 1536 + j0 + tx * 8 + j] = acc[i][j];
    }
}

// ---------------- projection: sg[b,o,q,l] = relu(sum_{k,c} g_w[o,c*3+k]*Y[b,k,q,c,l] + g_b[o])
// k=0 term folded in: Y0[b,q,c,l] = S[b,q,q] * xta[b,q,c,l]
__global__ __launch_bounds__(256) void proj_kernel(const float* __restrict__ gw,
                                                   const float* __restrict__ gb) {
    extern __shared__ float sm[];
    float* ysh = sm;            // 4*4608
    float* gws = sm + 18432;    // 12288, layout [r=(k*64+c)][o]
    __shared__ float sqq[4];
    int b = blockIdx.y, q0 = blockIdx.x * 4;
    int tid = threadIdx.x;
    if (tid < 4) sqq[tid] = g_Sscr[(size_t)b * 160000 + (size_t)(q0 + tid) * 401];
    __syncthreads();
    for (int i = tid; i < 12288; i += 256) {
        int r = i >> 6, o = i & 63;
        int k = r >> 6, c = r & 63;
        gws[i] = gw[o * 192 + c * 3 + k];
    }
    for (int i = tid; i < 18432; i += 256) {
        int qg = i / 4608;
        int rem = i - qg * 4608;
        int r = rem / 24, l = rem % 24;
        int k = r >> 6, c = r & 63;
        float v;
        if (k == 0) {
            v = sqq[qg] * g_xta[((size_t)(b * 400 + q0 + qg)) * 1536 + c * 24 + l];
        } else {
            v = g_Y[((size_t)(b * 2 + (k - 1)) * 400 + q0 + qg) * 1536 + c * 24 + l];
        }
        ysh[i] = v;
    }
    __syncthreads();
    int qg = tid >> 6;
    int t = tid & 63;
    int ob = (t >> 2) * 4, lgb = (t & 3) * 6;
    float acc[4][6];
#pragma unroll
    for (int i = 0; i < 4; i++) {
        float bi = gb[ob + i];
#pragma unroll
        for (int j = 0; j < 6; j++) acc[i][j] = bi;
    }
    const float* y = ysh + qg * 4608;
    for (int r = 0; r < 192; r++) {
        float w0 = gws[r * 64 + ob + 0];
        float w1 = gws[r * 64 + ob + 1];
        float w2 = gws[r * 64 + ob + 2];
        float w3 = gws[r * 64 + ob + 3];
#pragma unroll
        for (int j = 0; j < 6; j++) {
            float yv = y[r * 24 + lgb + j];
            acc[0][j] += w0 * yv;
            acc[1][j] += w1 * yv;
            acc[2][j] += w2 * yv;
            acc[3][j] += w3 * yv;
        }
    }
    int q = q0 + qg;
    float* out = g_sg + (size_t)b * 614400 + q * 24;
#pragma unroll
    for (int i = 0; i < 4; i++)
#pragma unroll
        for (int j = 0; j < 6; j++)
            out[(size_t)(ob + i) * 9600 + lgb + j] = fmaxf(acc[i][j], 0.f);
}

// ---------------- temporal conv + add x_input + relu + partial LN stats ----------------
__global__ __launch_bounds__(128) void tc_kernel(const float* __restrict__ tcw,
                                                 const float* __restrict__ tcb,
                                                 float* __restrict__ hout) {
    extern __shared__ float sm[];
    float* ws = sm;          // 12288
    float* sgs = sm + 12288; // 64*26 padded
    __shared__ float r1[128], r2[128];
    int n = blockIdx.x, b = blockIdx.y;
    int tid = threadIdx.x;
    for (int i = tid; i < 12288; i += 128) ws[i] = tcw[i];
    for (int i = tid; i < 1536; i += 128) {
        int ii = i / 24, l = i % 24;
        sgs[ii * 26 + 1 + l] = g_sg[(size_t)(b * 64 + ii) * 9600 + n * 24 + l];
    }
    if (tid < 64) { sgs[tid * 26] = 0.f; sgs[tid * 26 + 25] = 0.f; }
    __syncthreads();
    int o = (tid >> 2) * 2, lgb = (tid & 3) * 6;
    float acc0[6], acc1[6];
    float b0 = tcb[o], b1 = tcb[o + 1];
#pragma unroll
    for (int j = 0; j < 6; j++) { acc0[j] = b0; acc1[j] = b1; }
    for (int i = 0; i < 64; i++) {
        float w00 = ws[o * 192 + i * 3 + 0];
        float w01 = ws[o * 192 + i * 3 + 1];
        float w02 = ws[o * 192 + i * 3 + 2];
        float w10 = ws[(o + 1) * 192 + i * 3 + 0];
        float w11 = ws[(o + 1) * 192 + i * 3 + 1];
        float w12 = ws[(o + 1) * 192 + i * 3 + 2];
        float sv[8];
#pragma unroll
        for (int m = 0; m < 8; m++) sv[m] = sgs[i * 26 + lgb + m];
#pragma unroll
        for (int j = 0; j < 6; j++) {
            acc0[j] += w00 * sv[j] + w01 * sv[j + 1] + w02 * sv[j + 2];
            acc1[j] += w10 * sv[j] + w11 * sv[j + 1] + w12 * sv[j + 2];
        }
    }
    float s = 0.f, ss = 0.f;
    const float* xin = g_xin + (size_t)b * 614400 + n * 24;
    float* out = hout + (size_t)b * 614400 + n * 24;
#pragma unroll
    for (int j = 0; j < 6; j++) {
        float h0 = fmaxf(acc0[j] + xin[o * 9600 + lgb + j], 0.f);
        out[o * 9600 + lgb + j] = h0;
        s += h0; ss += h0 * h0;
        float h1 = fmaxf(acc1[j] + xin[(o + 1) * 9600 + lgb + j], 0.f);
        out[(o + 1) * 9600 + lgb + j] = h1;
        s += h1; ss += h1 * h1;
    }
    r1[tid] = s; r2[tid] = ss;
    __syncthreads();
    for (int st = 64; st > 0; st >>= 1) {
        if (tid < st) { r1[tid] += r1[tid + st]; r2[tid] += r2[tid + st]; }
        __syncthreads();
    }
    if (tid == 0) { g_psum[b * 400 + n] = r1[0]; g_psq[b * 400 + n] = r2[0]; }
}

// ---------------- per-batch stats (deterministic) ----------------
__global__ __launch_bounds__(256) void stats_kernel() {
    int b = blockIdx.x;
    int tid = threadIdx.x;
    __shared__ double d1[256], d2[256];
    double s = 0.0, ss = 0.0;
    for (int i = tid; i < 400; i += 256) { s += (double)g_psum[b * 400 + i]; ss += (double)g_psq[b * 400 + i]; }
    d1[tid] = s; d2[tid] = ss;
    __syncthreads();
    for (int st = 128; st > 0; st >>= 1) {
        if (tid < st) { d1[tid] += d1[tid + st]; d2[tid] += d2[tid + st]; }
        __syncthreads();
    }
    if (tid == 0) {
        double mu = d1[0] / 614400.0;
        double var = d2[0] / 614400.0 - mu * mu;
        g_mu[b] = (float)mu;
        g_rstd[b] = (float)(1.0 / sqrt(var + 1e-5));
    }
}

// ---------------- final layernorm (in place on d_out) ----------------
__global__ __launch_bounds__(256) void ln_kernel(float* __restrict__ out,
                                                 const float* __restrict__ lng,
                                                 const float* __restrict__ lnb) {
    size_t idx = (size_t)blockIdx.x * 256 + threadIdx.x;
    if (idx >= (size_t)SZ_X) return;
    int b = (int)(idx / 614400);
    int r = (int)(idx % 614400);
    out[idx] = (out[idx] - g_mu[b]) * g_rstd[b] * lng[r] + lnb[r];
}

// ---------------- copy S_coef / T_coef into d_out tail ----------------
__global__ __launch_bounds__(256) void copyout_kernel(float* __restrict__ out, int out_size) {
    if (out_size < SZ_TOTAL) return;
    size_t idx = (size_t)blockIdx.x * 256 + threadIdx.x;
    if (idx < (size_t)SZ_S) {
        out[OFF_S + idx] = g_Sscr[idx];
    } else if (idx < (size_t)(SZ_S + SZ_T)) {
        size_t t = idx - SZ_S;
        int b = (int)(t / 576);
        int rem = (int)(t % 576);
        int l = rem / 24, p = rem % 24;
        out[OFF_T + t] = g_T[b * 576 + p * 24 + l];  // T_coef[b,l,p] = T[b,p,l]
    }
}

// ---------------- launch ----------------
extern "C" void kernel_launch(void* const* d_in, const int* in_sizes, int n_in,
                              void* d_out, int out_size) {
    const float* x        = (const float*)d_in[0];
    const float* supports = (const float*)d_in[1];
    const float* conv1_w  = (const float*)d_in[2];
    const float* conv1_b  = (const float*)d_in[3];
    const float* t_cw1    = (const float*)d_in[4];
    const float* t_cw2    = (const float*)d_in[5];
    const float* t_w      = (const float*)d_in[6];
    const float* t_b      = (const float*)d_in[7];
    const float* t_v      = (const float*)d_in[8];
    const float* s_cw1    = (const float*)d_in[9];
    const float* s_cw2    = (const float*)d_in[10];
    const float* s_w      = (const float*)d_in[11];
    const float* s_b      = (const float*)d_in[12];
    const float* s_v      = (const float*)d_in[13];
    const float* g_w      = (const float*)d_in[14];
    const float* g_bv     = (const float*)d_in[15];
    const float* tc_w     = (const float*)d_in[16];
    const float* tc_b     = (const float*)d_in[17];
    const float* ln_g     = (const float*)d_in[18];
    const float* ln_b     = (const float*)d_in[19];
    float* out = (float*)d_out;

    cudaFuncSetAttribute(proj_kernel, cudaFuncAttributeMaxDynamicSharedMemorySize, 123 * 1024);
    cudaFuncSetAttribute(tc_kernel, cudaFuncAttributeMaxDynamicSharedMemorySize, 57 * 1024);

    // independent front-end passes
    conv1_kernel<<<dim3(400, 64), 128>>>(x, conv1_w, conv1_b);
    featA_kernel<<<dim3(400, 64), 256>>>(x, t_cw1, s_cw1, s_cw2);
    f2t_kernel<<<dim3(64, 64), 192>>>(x, t_cw2);
    tatt_kernel<<<64, 256>>>(t_w, t_b, t_v);
    xta_kernel<<<dim3(400, 64), 64>>>(x);
    gs_kernel<<<dim3(400, 64), 64>>>(s_w);

    // spatial attention
    tile64_kernel<1><<<dim3(7, 7, 64), 256>>>(nullptr, s_b, 400, 400, 64);
    tile64_kernel<0><<<dim3(7, 7, 1), 256>>>(supports, nullptr, 400, 400, 400);
    tile64_kernel<2><<<dim3(7, 7, 64), 256>>>(s_v, nullptr, 400, 400, 400);
    colmax_kernel<<<64, 512>>>();
    smax_kernel<<<dim3(400, 64), 256>>>();

    // cheby + projection (k=0 folded into proj)
    cheby_kernel<<<dim3(12, 4, 128), 256>>>(supports);
    proj_kernel<<<dim3(100, 64), 256, 122880>>>(g_w, g_bv);

    // temporal conv + residual + relu + LN
    tc_kernel<<<dim3(400, 64), 128, (12288 + 64 * 26) * 4>>>(tc_w, tc_b, out);
    stats_kernel<<<64, 256>>>();
    ln_kernel<<<153600, 256>>>(out, ln_g, ln_b);

    // emit S_coef / T_coef
    copyout_kernel<<<(SZ_S + SZ_T + 255) / 256, 256>>>(out, out_size);
}

// round 8
// speedup vs baseline: 1.2540x; 1.2540x over previous
#include <cuda_runtime.h>
#include <cuda_bf16.h>
#include <math.h>
#include <stddef.h>
#include <stdint.h>

// Problem dims: B=64, C=64, CO=64, N=400, L=24, K=3, KT=3
// x layout [b,c,n,l]: idx = ((b*64+c)*400+n)*24+l
#define SZ_X      39321600
#define SZ_S      10240000
#define SZ_T      36864
#define OFF_S     39321600
#define OFF_T     49561600
#define SZ_TOTAL  49598464

// ---------------- scratch ----------------
__device__ float g_xin[SZ_X];
__device__ float g_xta[SZ_X];            // x_TAt [b,n,c,l]
__device__ float g_Y[64*2*400*64*24];    // cheby k=1,2: [b,k-1,q, c*24+l]
__device__ float g_sg[SZ_X];
__device__ float g_f1t[64*24*400];
__device__ float g_f2t[64*64*24];
__device__ float g_f1s[64*400*24];
__device__ float g_f2s[64*64*400];
__device__ float g_gs[64*400*64];
__device__ float g_lsig[64*400*400];
__device__ float g_lg2s[64*400*400];
__device__ float g_Sscr[SZ_S];
__device__ float g_T[64*24*24];
__device__ float g_adj2[400*400];
__device__ float g_cmaxs[64*400];
__device__ float g_psum[64*400];
__device__ float g_psq[64*400];
__device__ float g_mu[64];
__device__ float g_rstd[64];

// ---------------- conv1 ----------------
__global__ __launch_bounds__(128) void conv1_kernel(const float* __restrict__ x,
                                                    const float* __restrict__ w,
                                                    const float* __restrict__ bias) {
    int n = blockIdx.x, b = blockIdx.y;
    __shared__ float xs[64 * 24];
    __shared__ float ws[64 * 64];
    int tid = threadIdx.x;
    const float* xb = x + (size_t)b * 614400;
    for (int i = tid; i < 1536; i += 128) {
        int c = i / 24, l = i % 24;
        xs[i] = xb[c * 9600 + n * 24 + l];
    }
    for (int i = tid; i < 4096; i += 128) ws[i] = w[i];
    __syncthreads();
    int o  = (tid >> 2) * 2;
    int lg = (tid & 3) * 6;
    float acc0[6], acc1[6];
    float b0 = bias[o], b1 = bias[o + 1];
#pragma unroll
    for (int j = 0; j < 6; j++) { acc0[j] = b0; acc1[j] = b1; }
    for (int c = 0; c < 64; c++) {
        float w0 = ws[o * 64 + c], w1 = ws[(o + 1) * 64 + c];
#pragma unroll
        for (int j = 0; j < 6; j++) {
            float xv = xs[c * 24 + lg + j];
            acc0[j] += w0 * xv;
            acc1[j] += w1 * xv;
        }
    }
    float* out = g_xin + (size_t)b * 614400 + n * 24;
#pragma unroll
    for (int j = 0; j < 6; j++) {
        out[o * 9600 + lg + j]       = acc0[j];
        out[(o + 1) * 9600 + lg + j] = acc1[j];
    }
}

// ---------------- fused features ----------------
__global__ __launch_bounds__(256) void featA_kernel(const float* __restrict__ x,
                                                    const float* __restrict__ tcw1,
                                                    const float* __restrict__ scw1,
                                                    const float* __restrict__ scw2) {
    int n = blockIdx.x, b = blockIdx.y;
    __shared__ float xs[1536];
    __shared__ float c1[64], c2[64], c3[24];
    int tid = threadIdx.x;
    const float* xb = x + (size_t)b * 614400;
    for (int i = tid; i < 1536; i += 256) {
        int c = i / 24, l = i % 24;
        xs[i] = xb[c * 9600 + n * 24 + l];
    }
    if (tid < 64) c1[tid] = tcw1[tid];
    else if (tid < 128) c2[tid - 64] = scw1[tid - 64];
    else if (tid < 152) c3[tid - 128] = scw2[tid - 128];
    __syncthreads();
    if (tid < 24) {
        int l = tid;
        float a1 = 0.f, a2 = 0.f;
        for (int c = 0; c < 64; c++) {
            float xv = xs[c * 24 + l];
            a1 += c1[c] * xv;
            a2 += c2[c] * xv;
        }
        g_f1t[(b * 24 + l) * 400 + n] = a1;
        g_f1s[(b * 400 + n) * 24 + l] = a2;
    } else if (tid >= 64 && tid < 128) {
        int c = tid - 64;
        float a = 0.f;
        for (int l = 0; l < 24; l++) a += c3[l] * xs[c * 24 + l];
        g_f2s[(b * 64 + c) * 400 + n] = a;
    }
}

// ---------------- f2t ----------------
__global__ __launch_bounds__(192) void f2t_kernel(const float* __restrict__ x,
                                                  const float* __restrict__ tcw2) {
    int c = blockIdx.x, b = blockIdx.y;
    __shared__ float red[192];
    int tid = threadIdx.x;
    int l = tid % 24, g = tid / 24;
    const float* xb = x + (size_t)b * 614400 + c * 9600;
    float a = 0.f;
    for (int n = g; n < 400; n += 8) a += tcw2[n] * xb[n * 24 + l];
    red[tid] = a;
    __syncthreads();
    if (tid < 24) {
        float s = 0.f;
        for (int gg = 0; gg < 8; gg++) s += red[gg * 24 + tid];
        g_f2t[(b * 64 + c) * 24 + tid] = s;
    }
}

// ---------------- temporal attention ----------------
__global__ __launch_bounds__(256) void tatt_kernel(const float* __restrict__ tw,
                                                   const float* __restrict__ tb,
                                                   const float* __restrict__ tv) {
    int b = blockIdx.x;
    __shared__ float f1tile[24 * 64], twtile[64 * 64], f2ts[64 * 24], gt[24 * 64];
    __shared__ float lg[576], lg2[576], cmax[24], rsum[24];
    int tid = threadIdx.x;
    for (int i = tid; i < 1536; i += 256) f2ts[i] = g_f2t[b * 1536 + i];

    int pg = tid >> 6;
    int c  = tid & 63;
    float acc[6] = {0.f, 0.f, 0.f, 0.f, 0.f, 0.f};
    for (int n0 = 0; n0 < 400; n0 += 64) {
        __syncthreads();
        for (int i = tid; i < 1536; i += 256) {
            int p = i >> 6, nn = i & 63;
            f1tile[i] = (n0 + nn < 400) ? g_f1t[(b * 24 + p) * 400 + n0 + nn] : 0.f;
        }
        for (int i = tid; i < 4096; i += 256) {
            int nn = i >> 6, cc = i & 63;
            twtile[i] = (n0 + nn < 400) ? tw[(n0 + nn) * 64 + cc] : 0.f;
        }
        __syncthreads();
        for (int nn = 0; nn < 64; nn++) {
            float wv = twtile[nn * 64 + c];
#pragma unroll
            for (int j = 0; j < 6; j++) acc[j] += f1tile[(pg * 6 + j) * 64 + nn] * wv;
        }
    }
    __syncthreads();
#pragma unroll
    for (int j = 0; j < 6; j++) gt[(pg * 6 + j) * 64 + c] = acc[j];
    __syncthreads();
    for (int i = tid; i < 576; i += 256) {
        int p = i / 24, l = i % 24;
        float s = tb[i];
        for (int cc = 0; cc < 64; cc++) s += gt[p * 64 + cc] * f2ts[cc * 24 + l];
        lg[i] = 1.f / (1.f + expf(-s));
    }
    __syncthreads();
    for (int i = tid; i < 576; i += 256) {
        int p = i / 24, l = i % 24;
        float s = 0.f;
        for (int q = 0; q < 24; q++) s += tv[p * 24 + q] * lg[q * 24 + l];
        lg2[i] = s;
    }
    __syncthreads();
    if (tid < 24) {
        float m = -1e30f;
        for (int p = 0; p < 24; p++) m = fmaxf(m, lg2[p * 24 + tid]);
        cmax[tid] = m;
    }
    __syncthreads();
    for (int i = tid; i < 576; i += 256) {
        int l = i % 24;
        lg[i] = expf(lg2[i] - cmax[l]);
    }
    __syncthreads();
    if (tid < 24) {
        float s = 0.f;
        for (int l = 0; l < 24; l++) s += lg[tid * 24 + l];
        rsum[tid] = s;
    }
    __syncthreads();
    for (int i = tid; i < 576; i += 256) {
        int p = i / 24;
        g_T[b * 576 + i] = lg[i] / rsum[p];
    }
}

// ---------------- x_TAt ----------------
__global__ __launch_bounds__(64) void xta_kernel(const float* __restrict__ x) {
    int n = blockIdx.x, b = blockIdx.y;
    __shared__ float xs[1536], Ts[576];
    int tid = threadIdx.x;
    const float* xb = x + (size_t)b * 614400;
    for (int i = tid; i < 1536; i += 64) {
        int c = i / 24, l = i % 24;
        xs[i] = xb[c * 9600 + n * 24 + l];
    }
    for (int i = tid; i < 576; i += 64) Ts[i] = g_T[b * 576 + i];
    __syncthreads();
    int cg = (tid >> 2) * 4, qg = (tid & 3) * 6;
    float acc[4][6] = {};
    for (int l = 0; l < 24; l++) {
        float tvv[6];
#pragma unroll
        for (int j = 0; j < 6; j++) tvv[j] = Ts[(qg + j) * 24 + l];
#pragma unroll
        for (int i = 0; i < 4; i++) {
            float xv = xs[(cg + i) * 24 + l];
#pragma unroll
            for (int j = 0; j < 6; j++) acc[i][j] += xv * tvv[j];
        }
    }
    float* o = g_xta + ((size_t)(b * 400 + n)) * 1536;
#pragma unroll
    for (int i = 0; i < 4; i++)
#pragma unroll
        for (int j = 0; j < 6; j++) o[(cg + i) * 24 + qg + j] = acc[i][j];
}

// ---------------- gs ----------------
__global__ __launch_bounds__(64) void gs_kernel(const float* __restrict__ sw) {
    int n = blockIdx.x, b = blockIdx.y;
    __shared__ float sws[24 * 64], f1row[24];
    int tid = threadIdx.x;
    for (int i = tid; i < 1536; i += 64) sws[i] = sw[i];
    if (tid < 24) f1row[tid] = g_f1s[(b * 400 + n) * 24 + tid];
    __syncthreads();
    float a = 0.f;
    for (int l = 0; l < 24; l++) a += f1row[l] * sws[l * 64 + tid];
    g_gs[(b * 400 + n) * 64 + tid] = a;
}

// ---------------- generic 64x64-tile SGEMM ----------------
// MODE 0: g_adj2 = A @ A ; MODE 1: lsig = sigmoid(gs@f2s + s_b); MODE 2: lg2s = s_v@lsig
template <int MODE>
__global__ __launch_bounds__(256) void tile64_kernel(const float* __restrict__ Aext,
                                                     const float* __restrict__ biasext,
                                                     int M, int N, int Kd) {
    int zb = blockIdx.z;
    const float* A;
    const float* Bm;
    float* C;
    if (MODE == 0) { A = Aext; Bm = Aext; C = g_adj2; }
    else if (MODE == 1) { A = g_gs + (size_t)zb * 25600; Bm = g_f2s + (size_t)zb * 25600; C = g_lsig + (size_t)zb * 160000; }
    else { A = Aext; Bm = g_lsig + (size_t)zb * 160000; C = g_lg2s + (size_t)zb * 160000; }

    int m0 = blockIdx.y * 64, n0 = blockIdx.x * 64;
    __shared__ float As[16][68], Bs[16][68];
    int tid = threadIdx.x;
    int tx = tid & 15, ty = tid >> 4;
    float acc[4][4] = {};
    for (int k0 = 0; k0 < Kd; k0 += 16) {
#pragma unroll
        for (int r = 0; r < 4; r++) {
            int lin = tid + 256 * r;
            int kk = lin & 15, m = lin >> 4;
            float v = 0.f;
            if (m0 + m < M && k0 + kk < Kd) v = A[(size_t)(m0 + m) * Kd + k0 + kk];
            As[kk][m] = v;
            int j = lin & 63, kk2 = lin >> 6;
            float v2 = 0.f;
            if (k0 + kk2 < Kd && n0 + j < N) v2 = Bm[(size_t)(k0 + kk2) * N + n0 + j];
            Bs[kk2][j] = v2;
        }
        __syncthreads();
#pragma unroll
        for (int kk = 0; kk < 16; kk++) {
            float a[4], bb[4];
#pragma unroll
            for (int i = 0; i < 4; i++) a[i] = As[kk][ty * 4 + i];
#pragma unroll
            for (int j = 0; j < 4; j++) bb[j] = Bs[kk][tx * 4 + j];
#pragma unroll
            for (int i = 0; i < 4; i++)
#pragma unroll
                for (int j = 0; j < 4; j++) acc[i][j] += a[i] * bb[j];
        }
        __syncthreads();
    }
#pragma unroll
    for (int i = 0; i < 4; i++) {
        int m = m0 + ty * 4 + i;
        if (m >= M) break;
#pragma unroll
        for (int j = 0; j < 4; j++) {
            int nn = n0 + tx * 4 + j;
            if (nn >= N) continue;
            float v = acc[i][j];
            if (MODE == 1) v = 1.f / (1.f + expf(-(v + biasext[(size_t)m * N + nn])));
            C[(size_t)m * N + nn] = v;
        }
    }
}

// ---------------- column max / softmax ----------------
__global__ __launch_bounds__(512) void colmax_kernel() {
    int b = blockIdx.x;
    int tid = threadIdx.x;
    if (tid < 400) {
        const float* base = g_lg2s + (size_t)b * 160000 + tid;
        float m = -1e30f;
        for (int p = 0; p < 400; p++) m = fmaxf(m, base[p * 400]);
        g_cmaxs[b * 400 + tid] = m;
    }
}

__global__ __launch_bounds__(256) void smax_kernel() {
    int p = blockIdx.x, b = blockIdx.y;
    int tid = threadIdx.x;
    __shared__ float red[256];
    const float* row = g_lg2s + (size_t)b * 160000 + p * 400;
    const float* cm = g_cmaxs + b * 400;
    float* orow = g_Sscr + (size_t)b * 160000 + p * 400;
    float s = 0.f;
    for (int n = tid; n < 400; n += 256) {
        float e = expf(row[n] - cm[n]);
        orow[n] = e;
        s += e;
    }
    red[tid] = s;
    __syncthreads();
    for (int st = 128; st > 0; st >>= 1) {
        if (tid < st) red[tid] += red[tid + st];
        __syncthreads();
    }
    float inv = 1.f / red[0];
    for (int n = tid; n < 400; n += 256) orow[n] *= inv;
}

// ======================================================================
// cheby via warp-level mma.sync (HMMA bf16, fp32 accum, hi/lo compensation)
//   Y[b,k-1] = (S .* Wk) @ xta[b]   400x400 @ 400x1536 per (b,k)
// grid: x = j-block (12 x 128), y = q-block (4 x 128), z = b*2 + (k-1)
// CTA: 256 thr = 8 warps in 2(M)x4(N); warp tile 64x32; frag m16n8k16
// K staged in 7 chunks of 64 (zero-padded); smem LDK=72 (pad) bf16.
// ======================================================================
#define CH_LDK 72
#define CH_ASZ (128 * CH_LDK)            // bf16 elements per array
#define CH_SMEM (4 * CH_ASZ * 2)         // 73728 bytes

__device__ __forceinline__ void mma16816(float* d, const uint32_t* a, const uint32_t* b) {
    asm volatile(
        "mma.sync.aligned.m16n8k16.row.col.f32.bf16.bf16.f32 "
        "{%0,%1,%2,%3}, {%4,%5,%6,%7}, {%8,%9}, {%0,%1,%2,%3};"
        : "+f"(d[0]), "+f"(d[1]), "+f"(d[2]), "+f"(d[3])
        : "r"(a[0]), "r"(a[1]), "r"(a[2]), "r"(a[3]), "r"(b[0]), "r"(b[1]));
}

__global__ __launch_bounds__(256) void cheby_mma_kernel(const float* __restrict__ adj) {
    extern __shared__ char chsm[];
    __nv_bfloat16* As_hi = (__nv_bfloat16*)chsm;
    __nv_bfloat16* As_lo = As_hi + CH_ASZ;
    __nv_bfloat16* Bs_hi = As_lo + CH_ASZ;
    __nv_bfloat16* Bs_lo = Bs_hi + CH_ASZ;

    int tid = threadIdx.x;
    int wid = tid >> 5, lane = tid & 31;
    int g = lane >> 2, tg = lane & 3;
    int b = blockIdx.z >> 1;
    int kvar = blockIdx.z & 1;           // 0 -> W1=adj, 1 -> W2=2*adj2-I
    int q0 = blockIdx.y * 128;
    int j0 = blockIdx.x * 128;
    const float* Sb = g_Sscr + (size_t)b * 160000;
    const float* Xb = g_xta + (size_t)b * 614400;
    int m_off = (wid >> 2) * 64;
    int n_off = (wid & 3) * 32;

    float acc[4][4][4];
#pragma unroll
    for (int im = 0; im < 4; im++)
#pragma unroll
        for (int in_ = 0; in_ < 4; in_++)
#pragma unroll
            for (int r = 0; r < 4; r++) acc[im][in_][r] = 0.f;

    for (int ch = 0; ch < 7; ch++) {
        int n0k = ch * 64;
        // ---- stage A (S .* Wk), hi/lo split; kk fastest for coalesced loads ----
#pragma unroll 4
        for (int i = 0; i < 32; i++) {
            int lin = tid + 256 * i;
            int kk = lin & 63, q = lin >> 6;
            int gq = q0 + q, gn = n0k + kk;
            float a = 0.f;
            if (gq < 400 && gn < 400) {
                float s = Sb[gq * 400 + gn];
                if (kvar == 0) a = s * adj[gq * 400 + gn];
                else a = s * (2.f * g_adj2[gq * 400 + gn] - (gq == gn ? 1.f : 0.f));
            }
            __nv_bfloat16 h = __float2bfloat16(a);
            __nv_bfloat16 l = __float2bfloat16(a - __bfloat162float(h));
            As_hi[q * CH_LDK + kk] = h;
            As_lo[q * CH_LDK + kk] = l;
        }
        // ---- stage B: Bs[j][kk] = X[n0k+kk][j0+j], hi/lo split ----
#pragma unroll 4
        for (int i = 0; i < 32; i++) {
            int lin = tid + 256 * i;
            int j = lin & 127, kk = lin >> 7;
            int gn = n0k + kk;
            float v = (gn < 400) ? Xb[(size_t)gn * 1536 + j0 + j] : 0.f;
            __nv_bfloat16 h = __float2bfloat16(v);
            __nv_bfloat16 l = __float2bfloat16(v - __bfloat162float(h));
            Bs_hi[j * CH_LDK + kk] = h;
            Bs_lo[j * CH_LDK + kk] = l;
        }
        __syncthreads();
        // ---- compute: 4 k16 steps ----
#pragma unroll
        for (int ks = 0; ks < 4; ks++) {
            int kb = ks * 16;
            uint32_t ah[4][4], al[4][4], bh[4][2], bl[4][2];
#pragma unroll
            for (int im = 0; im < 4; im++) {
                int r0 = m_off + im * 16 + g;
                int cA = kb + tg * 2;
                ah[im][0] = *(const uint32_t*)&As_hi[r0 * CH_LDK + cA];
                ah[im][1] = *(const uint32_t*)&As_hi[(r0 + 8) * CH_LDK + cA];
                ah[im][2] = *(const uint32_t*)&As_hi[r0 * CH_LDK + cA + 8];
                ah[im][3] = *(const uint32_t*)&As_hi[(r0 + 8) * CH_LDK + cA + 8];
                al[im][0] = *(const uint32_t*)&As_lo[r0 * CH_LDK + cA];
                al[im][1] = *(const uint32_t*)&As_lo[(r0 + 8) * CH_LDK + cA];
                al[im][2] = *(const uint32_t*)&As_lo[r0 * CH_LDK + cA + 8];
                al[im][3] = *(const uint32_t*)&As_lo[(r0 + 8) * CH_LDK + cA + 8];
            }
#pragma unroll
            for (int in_ = 0; in_ < 4; in_++) {
                int col = n_off + in_ * 8 + g;
                int rB = kb + tg * 2;
                bh[in_][0] = *(const uint32_t*)&Bs_hi[col * CH_LDK + rB];
                bh[in_][1] = *(const uint32_t*)&Bs_hi[col * CH_LDK + rB + 8];
                bl[in_][0] = *(const uint32_t*)&Bs_lo[col * CH_LDK + rB];
                bl[in_][1] = *(const uint32_t*)&Bs_lo[col * CH_LDK + rB + 8];
            }
#pragma unroll
            for (int im = 0; im < 4; im++)
#pragma unroll
                for (int in_ = 0; in_ < 4; in_++) {
                    mma16816(acc[im][in_], ah[im], bh[in_]);
                    mma16816(acc[im][in_], ah[im], bl[in_]);
                    mma16816(acc[im][in_], al[im], bh[in_]);
                }
        }
        __syncthreads();
    }

    // ---- writeback ----
    float* Yb = g_Y + (size_t)(b * 2 + kvar) * 614400;
#pragma unroll
    for (int im = 0; im < 4; im++) {
        int r0 = q0 + m_off + im * 16 + g;
#pragma unroll
        for (int in_ = 0; in_ < 4; in_++) {
            int col = j0 + n_off + in_ * 8 + tg * 2;
            if (r0 < 400) {
                float2 v = make_float2(acc[im][in_][0], acc[im][in_][1]);
                *(float2*)&Yb[(size_t)r0 * 1536 + col] = v;
            }
            if (r0 + 8 < 400) {
                float2 v = make_float2(acc[im][in_][2], acc[im][in_][3]);
                *(float2*)&Yb[(size_t)(r0 + 8) * 1536 + col] = v;
            }
        }
    }
}

// ======================================================================
// projection: sg[b,o,q,l] = relu(sum_{k,c} gw[o,c*3+k]*Yk[b,q,c,l] + gb[o])
// Y0 = S[q,q]*xta. 8 q per CTA, r=192 staged in 4 chunks of 48.
// ======================================================================
__global__ __launch_bounds__(256) void proj_kernel(const float* __restrict__ gw,
                                                   const float* __restrict__ gb) {
    extern __shared__ float sm[];
    float* gws = sm;            // 192*64
    float* ych = sm + 12288;    // 8*48*24
    __shared__ float sqq[8];
    int b = blockIdx.y, q0 = blockIdx.x * 8;
    int tid = threadIdx.x;
    if (tid < 8) sqq[tid] = g_Sscr[(size_t)b * 160000 + (size_t)(q0 + tid) * 401];
    for (int i = tid; i < 12288; i += 256) {
        int r = i >> 6, o = i & 63;
        int k = r >> 6, c = r & 63;
        gws[i] = gw[o * 192 + c * 3 + k];
    }
    int q  = tid >> 5;
    int t  = tid & 31;
    int ob  = (t >> 2) * 8;
    int lgb = (t & 3) * 6;
    float acc[8][6] = {};
    for (int rc = 0; rc < 4; rc++) {
        __syncthreads();
#pragma unroll
        for (int i = 0; i < 36; i++) {
            int lin = tid + 256 * i;
            int qq = lin / 1152;
            int rem = lin - qq * 1152;
            int r = rem / 24, l = rem - r * 24;
            int rg = rc * 48 + r;
            int k = rg >> 6, c = rg & 63;
            float v;
            if (k == 0)
                v = sqq[qq] * g_xta[((size_t)(b * 400 + q0 + qq)) * 1536 + c * 24 + l];
            else
                v = g_Y[((size_t)(b * 2 + (k - 1)) * 400 + q0 + qq) * 1536 + c * 24 + l];
            ych[lin] = v;
        }
        __syncthreads();
        const float* yb = ych + q * 1152;
        const float* wb = gws + rc * 48 * 64;
        for (int r = 0; r < 48; r++) {
            float yv[6], wv[8];
#pragma unroll
            for (int j = 0; j < 6; j++) yv[j] = yb[r * 24 + lgb + j];
#pragma unroll
            for (int i = 0; i < 8; i++) wv[i] = wb[r * 64 + ob + i];
#pragma unroll
            for (int i = 0; i < 8; i++)
#pragma unroll
                for (int j = 0; j < 6; j++) acc[i][j] += wv[i] * yv[j];
        }
    }
    float* out = g_sg + (size_t)b * 614400 + (q0 + q) * 24;
#pragma unroll
    for (int i = 0; i < 8; i++) {
        float bi = gb[ob + i];
#pragma unroll
        for (int j = 0; j < 6; j++)
            out[(size_t)(ob + i) * 9600 + lgb + j] = fmaxf(acc[i][j] + bi, 0.f);
    }
}

// ---------------- temporal conv + residual + relu + partial LN stats ----------------
__global__ __launch_bounds__(128) void tc_kernel(const float* __restrict__ tcw,
                                                 const float* __restrict__ tcb,
                                                 float* __restrict__ hout) {
    extern __shared__ float sm[];
    float* ws = sm;          // 12288
    float* sgs = sm + 12288; // 64*26
    __shared__ float r1[128], r2[128];
    int n = blockIdx.x, b = blockIdx.y;
    int tid = threadIdx.x;
    for (int i = tid; i < 12288; i += 128) ws[i] = tcw[i];
    for (int i = tid; i < 1536; i += 128) {
        int ii = i / 24, l = i % 24;
        sgs[ii * 26 + 1 + l] = g_sg[(size_t)(b * 64 + ii) * 9600 + n * 24 + l];
    }
    if (tid < 64) { sgs[tid * 26] = 0.f; sgs[tid * 26 + 25] = 0.f; }
    __syncthreads();
    int o = (tid >> 2) * 2, lgb = (tid & 3) * 6;
    float acc0[6], acc1[6];
    float b0 = tcb[o], b1 = tcb[o + 1];
#pragma unroll
    for (int j = 0; j < 6; j++) { acc0[j] = b0; acc1[j] = b1; }
    for (int i = 0; i < 64; i++) {
        float w00 = ws[o * 192 + i * 3 + 0];
        float w01 = ws[o * 192 + i * 3 + 1];
        float w02 = ws[o * 192 + i * 3 + 2];
        float w10 = ws[(o + 1) * 192 + i * 3 + 0];
        float w11 = ws[(o + 1) * 192 + i * 3 + 1];
        float w12 = ws[(o + 1) * 192 + i * 3 + 2];
        float sv[8];
#pragma unroll
        for (int m = 0; m < 8; m++) sv[m] = sgs[i * 26 + lgb + m];
#pragma unroll
        for (int j = 0; j < 6; j++) {
            acc0[j] += w00 * sv[j] + w01 * sv[j + 1] + w02 * sv[j + 2];
            acc1[j] += w10 * sv[j] + w11 * sv[j + 1] + w12 * sv[j + 2];
        }
    }
    float s = 0.f, ss = 0.f;
    const float* xin = g_xin + (size_t)b * 614400 + n * 24;
    float* out = hout + (size_t)b * 614400 + n * 24;
#pragma unroll
    for (int j = 0; j < 6; j++) {
        float h0 = fmaxf(acc0[j] + xin[o * 9600 + lgb + j], 0.f);
        out[o * 9600 + lgb + j] = h0;
        s += h0; ss += h0 * h0;
        float h1 = fmaxf(acc1[j] + xin[(o + 1) * 9600 + lgb + j], 0.f);
        out[(o + 1) * 9600 + lgb + j] = h1;
        s += h1; ss += h1 * h1;
    }
    r1[tid] = s; r2[tid] = ss;
    __syncthreads();
    for (int st = 64; st > 0; st >>= 1) {
        if (tid < st) { r1[tid] += r1[tid + st]; r2[tid] += r2[tid + st]; }
        __syncthreads();
    }
    if (tid == 0) { g_psum[b * 400 + n] = r1[0]; g_psq[b * 400 + n] = r2[0]; }
}

// ---------------- per-batch stats ----------------
__global__ __launch_bounds__(256) void stats_kernel() {
    int b = blockIdx.x;
    int tid = threadIdx.x;
    __shared__ double d1[256], d2[256];
    double s = 0.0, ss = 0.0;
    for (int i = tid; i < 400; i += 256) { s += (double)g_psum[b * 400 + i]; ss += (double)g_psq[b * 400 + i]; }
    d1[tid] = s; d2[tid] = ss;
    __syncthreads();
    for (int st = 128; st > 0; st >>= 1) {
        if (tid < st) { d1[tid] += d1[tid + st]; d2[tid] += d2[tid + st]; }
        __syncthreads();
    }
    if (tid == 0) {
        double mu = d1[0] / 614400.0;
        double var = d2[0] / 614400.0 - mu * mu;
        g_mu[b] = (float)mu;
        g_rstd[b] = (float)(1.0 / sqrt(var + 1e-5));
    }
}

// ---------------- final layernorm ----------------
__global__ __launch_bounds__(256) void ln_kernel(float* __restrict__ out,
                                                 const float* __restrict__ lng,
                                                 const float* __restrict__ lnb) {
    size_t idx = (size_t)blockIdx.x * 256 + threadIdx.x;
    if (idx >= (size_t)SZ_X) return;
    int b = (int)(idx / 614400);
    int r = (int)(idx % 614400);
    out[idx] = (out[idx] - g_mu[b]) * g_rstd[b] * lng[r] + lnb[r];
}

// ---------------- copy S_coef / T_coef ----------------
__global__ __launch_bounds__(256) void copyout_kernel(float* __restrict__ out, int out_size) {
    if (out_size < SZ_TOTAL) return;
    size_t idx = (size_t)blockIdx.x * 256 + threadIdx.x;
    if (idx < (size_t)SZ_S) {
        out[OFF_S + idx] = g_Sscr[idx];
    } else if (idx < (size_t)(SZ_S + SZ_T)) {
        size_t t = idx - SZ_S;
        int b = (int)(t / 576);
        int rem = (int)(t % 576);
        int l = rem / 24, p = rem % 24;
        out[OFF_T + t] = g_T[b * 576 + p * 24 + l];
    }
}

// ---------------- launch ----------------
extern "C" void kernel_launch(void* const* d_in, const int* in_sizes, int n_in,
                              void* d_out, int out_size) {
    const float* x        = (const float*)d_in[0];
    const float* supports = (const float*)d_in[1];
    const float* conv1_w  = (const float*)d_in[2];
    const float* conv1_b  = (const float*)d_in[3];
    const float* t_cw1    = (const float*)d_in[4];
    const float* t_cw2    = (const float*)d_in[5];
    const float* t_w      = (const float*)d_in[6];
    const float* t_b      = (const float*)d_in[7];
    const float* t_v      = (const float*)d_in[8];
    const float* s_cw1    = (const float*)d_in[9];
    const float* s_cw2    = (const float*)d_in[10];
    const float* s_w      = (const float*)d_in[11];
    const float* s_b      = (const float*)d_in[12];
    const float* s_v      = (const float*)d_in[13];
    const float* g_w      = (const float*)d_in[14];
    const float* g_bv     = (const float*)d_in[15];
    const float* tc_w     = (const float*)d_in[16];
    const float* tc_b     = (const float*)d_in[17];
    const float* ln_g     = (const float*)d_in[18];
    const float* ln_b     = (const float*)d_in[19];
    float* out = (float*)d_out;

    cudaFuncSetAttribute(cheby_mma_kernel, cudaFuncAttributeMaxDynamicSharedMemorySize, CH_SMEM);
    cudaFuncSetAttribute(proj_kernel, cudaFuncAttributeMaxDynamicSharedMemorySize, 90 * 1024);
    cudaFuncSetAttribute(tc_kernel, cudaFuncAttributeMaxDynamicSharedMemorySize, 57 * 1024);

    // independent front-end passes
    conv1_kernel<<<dim3(400, 64), 128>>>(x, conv1_w, conv1_b);
    featA_kernel<<<dim3(400, 64), 256>>>(x, t_cw1, s_cw1, s_cw2);
    f2t_kernel<<<dim3(64, 64), 192>>>(x, t_cw2);
    tatt_kernel<<<64, 256>>>(t_w, t_b, t_v);
    xta_kernel<<<dim3(400, 64), 64>>>(x);
    gs_kernel<<<dim3(400, 64), 64>>>(s_w);

    // spatial attention
    tile64_kernel<1><<<dim3(7, 7, 64), 256>>>(nullptr, s_b, 400, 400, 64);
    tile64_kernel<0><<<dim3(7, 7, 1), 256>>>(supports, nullptr, 400, 400, 400);
    tile64_kernel<2><<<dim3(7, 7, 64), 256>>>(s_v, nullptr, 400, 400, 400);
    colmax_kernel<<<64, 512>>>();
    smax_kernel<<<dim3(400, 64), 256>>>();

    // cheby (HMMA tensor cores) + projection (k=0 folded into proj)
    cheby_mma_kernel<<<dim3(12, 4, 128), 256, CH_SMEM>>>(supports);
    proj_kernel<<<dim3(50, 64), 256, (12288 + 9216) * 4>>>(g_w, g_bv);

    // temporal conv + residual + relu + LN
    tc_kernel<<<dim3(400, 64), 128, (12288 + 64 * 26) * 4>>>(tc_w, tc_b, out);
    stats_kernel<<<64, 256>>>();
    ln_kernel<<<153600, 256>>>(out, ln_g, ln_b);

    // emit S_coef / T_coef
    copyout_kernel<<<(SZ_S + SZ_T + 255) / 256, 256>>>(out, out_size);
}

// round 10
// speedup vs baseline: 1.6891x; 1.3469x over previous
#include <cuda_runtime.h>
#include <cuda_bf16.h>
#include <math.h>
#include <stddef.h>
#include <stdint.h>

// Problem dims: B=64, C=64, CO=64, N=400, L=24, K=3, KT=3
// x layout [b,c,n,l]: idx = ((b*64+c)*400+n)*24+l
#define SZ_X      39321600
#define SZ_S      10240000
#define SZ_T      36864
#define OFF_S     39321600
#define OFF_T     49561600
#define SZ_TOTAL  49598464

// ---------------- scratch ----------------
__device__ float g_xta[SZ_X];            // x_TAt [b,n,c,l]
__device__ float g_Y[64*2*400*64*24];    // cheby k=1,2: [b,k-1,q, c*24+l]
__device__ float g_sg[SZ_X];
__device__ float g_f1t[64*24*400];
__device__ float g_f2t[64*64*24];
__device__ float g_f1s[64*400*24];
__device__ float g_f2s[64*64*400];
__device__ float g_gs[64*400*64];
__device__ float g_lsig[64*400*400];
__device__ float g_lg2s[64*400*400];
__device__ float g_Sscr[SZ_S];
__device__ float g_T[64*24*24];
__device__ float g_adj2[400*400];
__device__ float g_cmaxs[64*400];
__device__ float g_psum[64*50];
__device__ float g_psq[64*50];
__device__ float g_mu[64];
__device__ float g_rstd[64];

// ---------------- fused features ----------------
__global__ __launch_bounds__(256) void featA_kernel(const float* __restrict__ x,
                                                    const float* __restrict__ tcw1,
                                                    const float* __restrict__ scw1,
                                                    const float* __restrict__ scw2) {
    int n = blockIdx.x, b = blockIdx.y;
    __shared__ float xs[1536];
    __shared__ float c1[64], c2[64], c3[24];
    int tid = threadIdx.x;
    const float* xb = x + (size_t)b * 614400;
    for (int i = tid; i < 1536; i += 256) {
        int c = i / 24, l = i % 24;
        xs[i] = xb[c * 9600 + n * 24 + l];
    }
    if (tid < 64) c1[tid] = tcw1[tid];
    else if (tid < 128) c2[tid - 64] = scw1[tid - 64];
    else if (tid < 152) c3[tid - 128] = scw2[tid - 128];
    __syncthreads();
    if (tid < 24) {
        int l = tid;
        float a1 = 0.f, a2 = 0.f;
        for (int c = 0; c < 64; c++) {
            float xv = xs[c * 24 + l];
            a1 += c1[c] * xv;
            a2 += c2[c] * xv;
        }
        g_f1t[(b * 24 + l) * 400 + n] = a1;
        g_f1s[(b * 400 + n) * 24 + l] = a2;
    } else if (tid >= 64 && tid < 128) {
        int c = tid - 64;
        float a = 0.f;
        for (int l = 0; l < 24; l++) a += c3[l] * xs[c * 24 + l];
        g_f2s[(b * 64 + c) * 400 + n] = a;
    }
}

// ---------------- f2t ----------------
__global__ __launch_bounds__(192) void f2t_kernel(const float* __restrict__ x,
                                                  const float* __restrict__ tcw2) {
    int c = blockIdx.x, b = blockIdx.y;
    __shared__ float red[192];
    int tid = threadIdx.x;
    int l = tid % 24, g = tid / 24;
    const float* xb = x + (size_t)b * 614400 + c * 9600;
    float a = 0.f;
    for (int n = g; n < 400; n += 8) a += tcw2[n] * xb[n * 24 + l];
    red[tid] = a;
    __syncthreads();
    if (tid < 24) {
        float s = 0.f;
        for (int gg = 0; gg < 8; gg++) s += red[gg * 24 + tid];
        g_f2t[(b * 64 + c) * 24 + tid] = s;
    }
}

// ---------------- temporal attention ----------------
__global__ __launch_bounds__(256) void tatt_kernel(const float* __restrict__ tw,
                                                   const float* __restrict__ tb,
                                                   const float* __restrict__ tv) {
    int b = blockIdx.x;
    __shared__ float f1tile[24 * 64], twtile[64 * 64], f2ts[64 * 24], gt[24 * 64];
    __shared__ float lg[576], lg2[576], cmax[24], rsum[24];
    int tid = threadIdx.x;
    for (int i = tid; i < 1536; i += 256) f2ts[i] = g_f2t[b * 1536 + i];

    int pg = tid >> 6;
    int c  = tid & 63;
    float acc[6] = {0.f, 0.f, 0.f, 0.f, 0.f, 0.f};
    for (int n0 = 0; n0 < 400; n0 += 64) {
        __syncthreads();
        for (int i = tid; i < 1536; i += 256) {
            int p = i >> 6, nn = i & 63;
            f1tile[i] = (n0 + nn < 400) ? g_f1t[(b * 24 + p) * 400 + n0 + nn] : 0.f;
        }
        for (int i = tid; i < 4096; i += 256) {
            int nn = i >> 6, cc = i & 63;
            twtile[i] = (n0 + nn < 400) ? tw[(n0 + nn) * 64 + cc] : 0.f;
        }
        __syncthreads();
        for (int nn = 0; nn < 64; nn++) {
            float wv = twtile[nn * 64 + c];
#pragma unroll
            for (int j = 0; j < 6; j++) acc[j] += f1tile[(pg * 6 + j) * 64 + nn] * wv;
        }
    }
    __syncthreads();
#pragma unroll
    for (int j = 0; j < 6; j++) gt[(pg * 6 + j) * 64 + c] = acc[j];
    __syncthreads();
    for (int i = tid; i < 576; i += 256) {
        int p = i / 24, l = i % 24;
        float s = tb[i];
        for (int cc = 0; cc < 64; cc++) s += gt[p * 64 + cc] * f2ts[cc * 24 + l];
        lg[i] = 1.f / (1.f + expf(-s));
    }
    __syncthreads();
    for (int i = tid; i < 576; i += 256) {
        int p = i / 24, l = i % 24;
        float s = 0.f;
        for (int q = 0; q < 24; q++) s += tv[p * 24 + q] * lg[q * 24 + l];
        lg2[i] = s;
    }
    __syncthreads();
    if (tid < 24) {
        float m = -1e30f;
        for (int p = 0; p < 24; p++) m = fmaxf(m, lg2[p * 24 + tid]);
        cmax[tid] = m;
    }
    __syncthreads();
    for (int i = tid; i < 576; i += 256) {
        int l = i % 24;
        lg[i] = expf(lg2[i] - cmax[l]);
    }
    __syncthreads();
    if (tid < 24) {
        float s = 0.f;
        for (int l = 0; l < 24; l++) s += lg[tid * 24 + l];
        rsum[tid] = s;
    }
    __syncthreads();
    for (int i = tid; i < 576; i += 256) {
        int p = i / 24;
        g_T[b * 576 + i] = lg[i] / rsum[p];
    }
}

// ---------------- x_TAt ----------------
__global__ __launch_bounds__(64) void xta_kernel(const float* __restrict__ x) {
    int n = blockIdx.x, b = blockIdx.y;
    __shared__ float xs[1536], Ts[576];
    int tid = threadIdx.x;
    const float* xb = x + (size_t)b * 614400;
    for (int i = tid; i < 1536; i += 64) {
        int c = i / 24, l = i % 24;
        xs[i] = xb[c * 9600 + n * 24 + l];
    }
    for (int i = tid; i < 576; i += 64) Ts[i] = g_T[b * 576 + i];
    __syncthreads();
    int cg = (tid >> 2) * 4, qg = (tid & 3) * 6;
    float acc[4][6] = {};
    for (int l = 0; l < 24; l++) {
        float tvv[6];
#pragma unroll
        for (int j = 0; j < 6; j++) tvv[j] = Ts[(qg + j) * 24 + l];
#pragma unroll
        for (int i = 0; i < 4; i++) {
            float xv = xs[(cg + i) * 24 + l];
#pragma unroll
            for (int j = 0; j < 6; j++) acc[i][j] += xv * tvv[j];
        }
    }
    float* o = g_xta + ((size_t)(b * 400 + n)) * 1536;
#pragma unroll
    for (int i = 0; i < 4; i++)
#pragma unroll
        for (int j = 0; j < 6; j++) o[(cg + i) * 24 + qg + j] = acc[i][j];
}

// ---------------- gs ----------------
__global__ __launch_bounds__(64) void gs_kernel(const float* __restrict__ sw) {
    int n = blockIdx.x, b = blockIdx.y;
    __shared__ float sws[24 * 64], f1row[24];
    int tid = threadIdx.x;
    for (int i = tid; i < 1536; i += 64) sws[i] = sw[i];
    if (tid < 24) f1row[tid] = g_f1s[(b * 400 + n) * 24 + tid];
    __syncthreads();
    float a = 0.f;
    for (int l = 0; l < 24; l++) a += f1row[l] * sws[l * 64 + tid];
    g_gs[(b * 400 + n) * 64 + tid] = a;
}

// ---------------- generic 64x64-tile SGEMM ----------------
// MODE 0: g_adj2 = A @ A ; MODE 1: lsig = sigmoid(gs@f2s + s_b); MODE 2: lg2s = s_v@lsig
template <int MODE>
__global__ __launch_bounds__(256) void tile64_kernel(const float* __restrict__ Aext,
                                                     const float* __restrict__ biasext,
                                                     int M, int N, int Kd) {
    int zb = blockIdx.z;
    const float* A;
    const float* Bm;
    float* C;
    if (MODE == 0) { A = Aext; Bm = Aext; C = g_adj2; }
    else if (MODE == 1) { A = g_gs + (size_t)zb * 25600; Bm = g_f2s + (size_t)zb * 25600; C = g_lsig + (size_t)zb * 160000; }
    else { A = Aext; Bm = g_lsig + (size_t)zb * 160000; C = g_lg2s + (size_t)zb * 160000; }

    int m0 = blockIdx.y * 64, n0 = blockIdx.x * 64;
    __shared__ float As[16][68], Bs[16][68];
    int tid = threadIdx.x;
    int tx = tid & 15, ty = tid >> 4;
    float acc[4][4] = {};
    for (int k0 = 0; k0 < Kd; k0 += 16) {
#pragma unroll
        for (int r = 0; r < 4; r++) {
            int lin = tid + 256 * r;
            int kk = lin & 15, m = lin >> 4;
            float v = 0.f;
            if (m0 + m < M && k0 + kk < Kd) v = A[(size_t)(m0 + m) * Kd + k0 + kk];
            As[kk][m] = v;
            int j = lin & 63, kk2 = lin >> 6;
            float v2 = 0.f;
            if (k0 + kk2 < Kd && n0 + j < N) v2 = Bm[(size_t)(k0 + kk2) * N + n0 + j];
            Bs[kk2][j] = v2;
        }
        __syncthreads();
#pragma unroll
        for (int kk = 0; kk < 16; kk++) {
            float a[4], bb[4];
#pragma unroll
            for (int i = 0; i < 4; i++) a[i] = As[kk][ty * 4 + i];
#pragma unroll
            for (int j = 0; j < 4; j++) bb[j] = Bs[kk][tx * 4 + j];
#pragma unroll
            for (int i = 0; i < 4; i++)
#pragma unroll
                for (int j = 0; j < 4; j++) acc[i][j] += a[i] * bb[j];
        }
        __syncthreads();
    }
#pragma unroll
    for (int i = 0; i < 4; i++) {
        int m = m0 + ty * 4 + i;
        if (m >= M) break;
#pragma unroll
        for (int j = 0; j < 4; j++) {
            int nn = n0 + tx * 4 + j;
            if (nn >= N) continue;
            float v = acc[i][j];
            if (MODE == 1) v = 1.f / (1.f + expf(-(v + biasext[(size_t)m * N + nn])));
            C[(size_t)m * N + nn] = v;
        }
    }
}

// ---------------- column max / softmax ----------------
__global__ __launch_bounds__(512) void colmax_kernel() {
    int b = blockIdx.x;
    int tid = threadIdx.x;
    if (tid < 400) {
        const float* base = g_lg2s + (size_t)b * 160000 + tid;
        float m = -1e30f;
        for (int p = 0; p < 400; p++) m = fmaxf(m, base[p * 400]);
        g_cmaxs[b * 400 + tid] = m;
    }
}

__global__ __launch_bounds__(256) void smax_kernel() {
    int p = blockIdx.x, b = blockIdx.y;
    int tid = threadIdx.x;
    __shared__ float red[256];
    const float* row = g_lg2s + (size_t)b * 160000 + p * 400;
    const float* cm = g_cmaxs + b * 400;
    float* orow = g_Sscr + (size_t)b * 160000 + p * 400;
    float s = 0.f;
    for (int n = tid; n < 400; n += 256) {
        float e = expf(row[n] - cm[n]);
        orow[n] = e;
        s += e;
    }
    red[tid] = s;
    __syncthreads();
    for (int st = 128; st > 0; st >>= 1) {
        if (tid < st) red[tid] += red[tid + st];
        __syncthreads();
    }
    float inv = 1.f / red[0];
    for (int n = tid; n < 400; n += 256) orow[n] *= inv;
}

// ---------------- HMMA helper ----------------
__device__ __forceinline__ void mma16816(float* d, const uint32_t* a, const uint32_t* b) {
    asm volatile(
        "mma.sync.aligned.m16n8k16.row.col.f32.bf16.bf16.f32 "
        "{%0,%1,%2,%3}, {%4,%5,%6,%7}, {%8,%9}, {%0,%1,%2,%3};"
        : "+f"(d[0]), "+f"(d[1]), "+f"(d[2]), "+f"(d[3])
        : "r"(a[0]), "r"(a[1]), "r"(a[2]), "r"(a[3]), "r"(b[0]), "r"(b[1]));
}

// ======================================================================
// cheby via warp-level mma.sync (HMMA bf16, fp32 accum, hi/lo compensation)
// ======================================================================
#define CH_LDK 72
#define CH_ASZ (128 * CH_LDK)
#define CH_SMEM (4 * CH_ASZ * 2)

__global__ __launch_bounds__(256) void cheby_mma_kernel(const float* __restrict__ adj) {
    extern __shared__ char chsm[];
    __nv_bfloat16* As_hi = (__nv_bfloat16*)chsm;
    __nv_bfloat16* As_lo = As_hi + CH_ASZ;
    __nv_bfloat16* Bs_hi = As_lo + CH_ASZ;
    __nv_bfloat16* Bs_lo = Bs_hi + CH_ASZ;

    int tid = threadIdx.x;
    int wid = tid >> 5, lane = tid & 31;
    int g = lane >> 2, tg = lane & 3;
    int b = blockIdx.z >> 1;
    int kvar = blockIdx.z & 1;
    int q0 = blockIdx.y * 128;
    int j0 = blockIdx.x * 128;
    const float* Sb = g_Sscr + (size_t)b * 160000;
    const float* Xb = g_xta + (size_t)b * 614400;
    int m_off = (wid >> 2) * 64;
    int n_off = (wid & 3) * 32;

    float acc[4][4][4];
#pragma unroll
    for (int im = 0; im < 4; im++)
#pragma unroll
        for (int in_ = 0; in_ < 4; in_++)
#pragma unroll
            for (int r = 0; r < 4; r++) acc[im][in_][r] = 0.f;

    for (int ch = 0; ch < 7; ch++) {
        int n0k = ch * 64;
#pragma unroll 4
        for (int i = 0; i < 32; i++) {
            int lin = tid + 256 * i;
            int kk = lin & 63, q = lin >> 6;
            int gq = q0 + q, gn = n0k + kk;
            float a = 0.f;
            if (gq < 400 && gn < 400) {
                float s = Sb[gq * 400 + gn];
                if (kvar == 0) a = s * adj[gq * 400 + gn];
                else a = s * (2.f * g_adj2[gq * 400 + gn] - (gq == gn ? 1.f : 0.f));
            }
            __nv_bfloat16 h = __float2bfloat16(a);
            __nv_bfloat16 l = __float2bfloat16(a - __bfloat162float(h));
            As_hi[q * CH_LDK + kk] = h;
            As_lo[q * CH_LDK + kk] = l;
        }
#pragma unroll 4
        for (int i = 0; i < 32; i++) {
            int lin = tid + 256 * i;
            int j = lin & 127, kk = lin >> 7;
            int gn = n0k + kk;
            float v = (gn < 400) ? Xb[(size_t)gn * 1536 + j0 + j] : 0.f;
            __nv_bfloat16 h = __float2bfloat16(v);
            __nv_bfloat16 l = __float2bfloat16(v - __bfloat162float(h));
            Bs_hi[j * CH_LDK + kk] = h;
            Bs_lo[j * CH_LDK + kk] = l;
        }
        __syncthreads();
#pragma unroll
        for (int ks = 0; ks < 4; ks++) {
            int kb = ks * 16;
            uint32_t ah[4][4], al[4][4], bh[4][2], bl[4][2];
#pragma unroll
            for (int im = 0; im < 4; im++) {
                int r0 = m_off + im * 16 + g;
                int cA = kb + tg * 2;
                ah[im][0] = *(const uint32_t*)&As_hi[r0 * CH_LDK + cA];
                ah[im][1] = *(const uint32_t*)&As_hi[(r0 + 8) * CH_LDK + cA];
                ah[im][2] = *(const uint32_t*)&As_hi[r0 * CH_LDK + cA + 8];
                ah[im][3] = *(const uint32_t*)&As_hi[(r0 + 8) * CH_LDK + cA + 8];
                al[im][0] = *(const uint32_t*)&As_lo[r0 * CH_LDK + cA];
                al[im][1] = *(const uint32_t*)&As_lo[(r0 + 8) * CH_LDK + cA];
                al[im][2] = *(const uint32_t*)&As_lo[r0 * CH_LDK + cA + 8];
                al[im][3] = *(const uint32_t*)&As_lo[(r0 + 8) * CH_LDK + cA + 8];
            }
#pragma unroll
            for (int in_ = 0; in_ < 4; in_++) {
                int col = n_off + in_ * 8 + g;
                int rB = kb + tg * 2;
                bh[in_][0] = *(const uint32_t*)&Bs_hi[col * CH_LDK + rB];
                bh[in_][1] = *(const uint32_t*)&Bs_hi[col * CH_LDK + rB + 8];
                bl[in_][0] = *(const uint32_t*)&Bs_lo[col * CH_LDK + rB];
                bl[in_][1] = *(const uint32_t*)&Bs_lo[col * CH_LDK + rB + 8];
            }
#pragma unroll
            for (int im = 0; im < 4; im++)
#pragma unroll
                for (int in_ = 0; in_ < 4; in_++) {
                    mma16816(acc[im][in_], ah[im], bh[in_]);
                    mma16816(acc[im][in_], ah[im], bl[in_]);
                    mma16816(acc[im][in_], al[im], bh[in_]);
                }
        }
        __syncthreads();
    }

    float* Yb = g_Y + (size_t)(b * 2 + kvar) * 614400;
#pragma unroll
    for (int im = 0; im < 4; im++) {
        int r0 = q0 + m_off + im * 16 + g;
#pragma unroll
        for (int in_ = 0; in_ < 4; in_++) {
            int col = j0 + n_off + in_ * 8 + tg * 2;
            if (r0 < 400) {
                float2 v = make_float2(acc[im][in_][0], acc[im][in_][1]);
                *(float2*)&Yb[(size_t)r0 * 1536 + col] = v;
            }
            if (r0 + 8 < 400) {
                float2 v = make_float2(acc[im][in_][2], acc[im][in_][3]);
                *(float2*)&Yb[(size_t)(r0 + 8) * 1536 + col] = v;
            }
        }
    }
}

// ======================================================================
// proj via HMMA:  sg[b,o,q,l] = relu(W[64x192] @ Y[192x(q,l)] + gb[o])
// K chunks = k (0: S[q,q]*xta, 1,2: g_Y). Per CTA: 8 q (N=192), 8 warps,
// each warp owns one q (24 cols = 3 n-frags), full M=64 (4 m-frags).
// ======================================================================
#define PJ_LDA 66
#define PJ_ASZ (64 * PJ_LDA)     // 4224
#define PJ_BSZ (192 * PJ_LDA)    // 12672
#define PJ_SMEM ((2 * PJ_ASZ + 2 * PJ_BSZ) * 2)  // 67584 bytes

__global__ __launch_bounds__(256) void proj_mma_kernel(const float* __restrict__ gw,
                                                       const float* __restrict__ gb) {
    extern __shared__ char pjsm[];
    __nv_bfloat16* Ah = (__nv_bfloat16*)pjsm;
    __nv_bfloat16* Al = Ah + PJ_ASZ;
    __nv_bfloat16* Bh = Al + PJ_ASZ;
    __nv_bfloat16* Bl = Bh + PJ_BSZ;
    __shared__ float sqq[8];
    int tid = threadIdx.x;
    int wid = tid >> 5, lane = tid & 31;
    int g = lane >> 2, tg = lane & 3;
    int b = blockIdx.y, q0 = blockIdx.x * 8;
    if (tid < 8) sqq[tid] = g_Sscr[(size_t)b * 160000 + (size_t)(q0 + tid) * 401];
    __syncthreads();

    float acc[4][3][4];
#pragma unroll
    for (int mf = 0; mf < 4; mf++)
#pragma unroll
        for (int nf = 0; nf < 3; nf++)
#pragma unroll
            for (int r = 0; r < 4; r++) acc[mf][nf][r] = 0.f;

    for (int k = 0; k < 3; k++) {
        // stage A: As[o][c] = gw[o*192 + c*3 + k]
        for (int i = tid; i < 4096; i += 256) {
            int o = i >> 6, c = i & 63;
            float v = gw[o * 192 + c * 3 + k];
            __nv_bfloat16 h = __float2bfloat16(v);
            Ah[o * PJ_LDA + c] = h;
            Al[o * PJ_LDA + c] = __float2bfloat16(v - __bfloat162float(h));
        }
        // stage B: Bs[(q*24+l)][c] = Yk[b,q0+q,c,l]
#pragma unroll 4
        for (int i = 0; i < 48; i++) {
            int lin = tid + 256 * i;
            int q = lin / 1536;
            int rem = lin - q * 1536;
            int c = rem / 24, l = rem - c * 24;
            float v;
            if (k == 0)
                v = sqq[q] * g_xta[((size_t)(b * 400 + q0 + q)) * 1536 + c * 24 + l];
            else
                v = g_Y[((size_t)(b * 2 + (k - 1)) * 400 + q0 + q) * 1536 + c * 24 + l];
            __nv_bfloat16 h = __float2bfloat16(v);
            int col = q * 24 + l;
            Bh[col * PJ_LDA + c] = h;
            Bl[col * PJ_LDA + c] = __float2bfloat16(v - __bfloat162float(h));
        }
        __syncthreads();
#pragma unroll
        for (int ks = 0; ks < 4; ks++) {
            int kb = ks * 16;
            uint32_t ah[4][4], al[4][4], bh[3][2], bl[3][2];
#pragma unroll
            for (int mf = 0; mf < 4; mf++) {
                int r0 = mf * 16 + g;
                int cA = kb + tg * 2;
                ah[mf][0] = *(const uint32_t*)&Ah[r0 * PJ_LDA + cA];
                ah[mf][1] = *(const uint32_t*)&Ah[(r0 + 8) * PJ_LDA + cA];
                ah[mf][2] = *(const uint32_t*)&Ah[r0 * PJ_LDA + cA + 8];
                ah[mf][3] = *(const uint32_t*)&Ah[(r0 + 8) * PJ_LDA + cA + 8];
                al[mf][0] = *(const uint32_t*)&Al[r0 * PJ_LDA + cA];
                al[mf][1] = *(const uint32_t*)&Al[(r0 + 8) * PJ_LDA + cA];
                al[mf][2] = *(const uint32_t*)&Al[r0 * PJ_LDA + cA + 8];
                al[mf][3] = *(const uint32_t*)&Al[(r0 + 8) * PJ_LDA + cA + 8];
            }
#pragma unroll
            for (int nf = 0; nf < 3; nf++) {
                int col = wid * 24 + nf * 8 + g;
                int rB = kb + tg * 2;
                bh[nf][0] = *(const uint32_t*)&Bh[col * PJ_LDA + rB];
                bh[nf][1] = *(const uint32_t*)&Bh[col * PJ_LDA + rB + 8];
                bl[nf][0] = *(const uint32_t*)&Bl[col * PJ_LDA + rB];
                bl[nf][1] = *(const uint32_t*)&Bl[col * PJ_LDA + rB + 8];
            }
#pragma unroll
            for (int mf = 0; mf < 4; mf++)
#pragma unroll
                for (int nf = 0; nf < 3; nf++) {
                    mma16816(acc[mf][nf], ah[mf], bh[nf]);
                    mma16816(acc[mf][nf], ah[mf], bl[nf]);
                    mma16816(acc[mf][nf], al[mf], bh[nf]);
                }
        }
        __syncthreads();
    }

    // epilogue: warp owns q = q0 + wid
    int q = q0 + wid;
#pragma unroll
    for (int mf = 0; mf < 4; mf++) {
        int o0 = mf * 16 + g;
        float b0 = gb[o0], b1 = gb[o0 + 8];
#pragma unroll
        for (int nf = 0; nf < 3; nf++) {
            int l = nf * 8 + tg * 2;
            float2 v0 = make_float2(fmaxf(acc[mf][nf][0] + b0, 0.f),
                                    fmaxf(acc[mf][nf][1] + b0, 0.f));
            *(float2*)&g_sg[(size_t)(b * 64 + o0) * 9600 + q * 24 + l] = v0;
            float2 v1 = make_float2(fmaxf(acc[mf][nf][2] + b1, 0.f),
                                    fmaxf(acc[mf][nf][3] + b1, 0.f));
            *(float2*)&g_sg[(size_t)(b * 64 + o0 + 8) * 9600 + q * 24 + l] = v1;
        }
    }
}

// ======================================================================
// temporal conv + residual (conv1 fused as 4th K chunk) via HMMA
// out[o,(n,l)] = relu( sum_{c,t} tcw[o,c,t]*sg[c,n,l+t-1]
//                    + sum_c conv1_w[o,c]*x[c,n,l] + tcb[o] + conv1_b[o] )
// chunks 0..2: t taps of sg; chunk 3: conv1 on x. Epilogue: LN partials.
// ======================================================================
__global__ __launch_bounds__(256) void tc_mma_kernel(const float* __restrict__ x,
                                                     const float* __restrict__ tcw,
                                                     const float* __restrict__ tcb,
                                                     const float* __restrict__ c1w,
                                                     const float* __restrict__ c1b,
                                                     float* __restrict__ hout) {
    extern __shared__ char tcsm[];
    __nv_bfloat16* Ah = (__nv_bfloat16*)tcsm;
    __nv_bfloat16* Al = Ah + PJ_ASZ;
    __nv_bfloat16* Bh = Al + PJ_ASZ;
    __nv_bfloat16* Bl = Bh + PJ_BSZ;
    __shared__ float r1[256], r2[256];
    int tid = threadIdx.x;
    int wid = tid >> 5, lane = tid & 31;
    int g = lane >> 2, tg = lane & 3;
    int b = blockIdx.y, n0 = blockIdx.x * 8;

    float acc[4][3][4];
#pragma unroll
    for (int mf = 0; mf < 4; mf++)
#pragma unroll
        for (int nf = 0; nf < 3; nf++)
#pragma unroll
            for (int r = 0; r < 4; r++) acc[mf][nf][r] = 0.f;

    for (int kc = 0; kc < 4; kc++) {
        // stage A
        for (int i = tid; i < 4096; i += 256) {
            int o = i >> 6, c = i & 63;
            float v = (kc < 3) ? tcw[o * 192 + c * 3 + kc] : c1w[o * 64 + c];
            __nv_bfloat16 h = __float2bfloat16(v);
            Ah[o * PJ_LDA + c] = h;
            Al[o * PJ_LDA + c] = __float2bfloat16(v - __bfloat162float(h));
        }
        // stage B
#pragma unroll 4
        for (int i = 0; i < 48; i++) {
            int lin = tid + 256 * i;
            int q = lin / 1536;
            int rem = lin - q * 1536;
            int c = rem / 24, l = rem - c * 24;
            float v;
            if (kc < 3) {
                int ls = l + kc - 1;
                v = (ls >= 0 && ls < 24)
                        ? g_sg[(size_t)(b * 64 + c) * 9600 + (n0 + q) * 24 + ls]
                        : 0.f;
            } else {
                v = x[((size_t)(b * 64 + c) * 400 + n0 + q) * 24 + l];
            }
            __nv_bfloat16 h = __float2bfloat16(v);
            int col = q * 24 + l;
            Bh[col * PJ_LDA + c] = h;
            Bl[col * PJ_LDA + c] = __float2bfloat16(v - __bfloat162float(h));
        }
        __syncthreads();
#pragma unroll
        for (int ks = 0; ks < 4; ks++) {
            int kb = ks * 16;
            uint32_t ah[4][4], al[4][4], bh[3][2], bl[3][2];
#pragma unroll
            for (int mf = 0; mf < 4; mf++) {
                int r0 = mf * 16 + g;
                int cA = kb + tg * 2;
                ah[mf][0] = *(const uint32_t*)&Ah[r0 * PJ_LDA + cA];
                ah[mf][1] = *(const uint32_t*)&Ah[(r0 + 8) * PJ_LDA + cA];
                ah[mf][2] = *(const uint32_t*)&Ah[r0 * PJ_LDA + cA + 8];
                ah[mf][3] = *(const uint32_t*)&Ah[(r0 + 8) * PJ_LDA + cA + 8];
                al[mf][0] = *(const uint32_t*)&Al[r0 * PJ_LDA + cA];
                al[mf][1] = *(const uint32_t*)&Al[(r0 + 8) * PJ_LDA + cA];
                al[mf][2] = *(const uint32_t*)&Al[r0 * PJ_LDA + cA + 8];
                al[mf][3] = *(const uint32_t*)&Al[(r0 + 8) * PJ_LDA + cA + 8];
            }
#pragma unroll
            for (int nf = 0; nf < 3; nf++) {
                int col = wid * 24 + nf * 8 + g;
                int rB = kb + tg * 2;
                bh[nf][0] = *(const uint32_t*)&Bh[col * PJ_LDA + rB];
                bh[nf][1] = *(const uint32_t*)&Bh[col * PJ_LDA + rB + 8];
                bl[nf][0] = *(const uint32_t*)&Bl[col * PJ_LDA + rB];
                bl[nf][1] = *(const uint32_t*)&Bl[col * PJ_LDA + rB + 8];
            }
#pragma unroll
            for (int mf = 0; mf < 4; mf++)
#pragma unroll
                for (int nf = 0; nf < 3; nf++) {
                    mma16816(acc[mf][nf], ah[mf], bh[nf]);
                    mma16816(acc[mf][nf], ah[mf], bl[nf]);
                    mma16816(acc[mf][nf], al[mf], bh[nf]);
                }
        }
        __syncthreads();
    }

    // epilogue: warp owns n = n0 + wid; bias + relu + LN partials
    int n = n0 + wid;
    float s = 0.f, ss = 0.f;
#pragma unroll
    for (int mf = 0; mf < 4; mf++) {
        int o0 = mf * 16 + g;
        float b0 = tcb[o0] + c1b[o0];
        float b1 = tcb[o0 + 8] + c1b[o0 + 8];
#pragma unroll
        for (int nf = 0; nf < 3; nf++) {
            int l = nf * 8 + tg * 2;
            float h0 = fmaxf(acc[mf][nf][0] + b0, 0.f);
            float h1 = fmaxf(acc[mf][nf][1] + b0, 0.f);
            float h2 = fmaxf(acc[mf][nf][2] + b1, 0.f);
            float h3 = fmaxf(acc[mf][nf][3] + b1, 0.f);
            *(float2*)&hout[(size_t)(b * 64 + o0) * 9600 + n * 24 + l] = make_float2(h0, h1);
            *(float2*)&hout[(size_t)(b * 64 + o0 + 8) * 9600 + n * 24 + l] = make_float2(h2, h3);
            s += h0 + h1 + h2 + h3;
            ss += h0 * h0 + h1 * h1 + h2 * h2 + h3 * h3;
        }
    }
    r1[tid] = s; r2[tid] = ss;
    __syncthreads();
    for (int st = 128; st > 0; st >>= 1) {
        if (tid < st) { r1[tid] += r1[tid + st]; r2[tid] += r2[tid + st]; }
        __syncthreads();
    }
    if (tid == 0) {
        g_psum[b * 50 + blockIdx.x] = r1[0];
        g_psq[b * 50 + blockIdx.x] = r2[0];
    }
}

// ---------------- per-batch stats ----------------
__global__ __launch_bounds__(256) void stats_kernel() {
    int b = blockIdx.x;
    int tid = threadIdx.x;
    __shared__ double d1[256], d2[256];
    double s = 0.0, ss = 0.0;
    for (int i = tid; i < 50; i += 256) { s += (double)g_psum[b * 50 + i]; ss += (double)g_psq[b * 50 + i]; }
    d1[tid] = s; d2[tid] = ss;
    __syncthreads();
    for (int st = 128; st > 0; st >>= 1) {
        if (tid < st) { d1[tid] += d1[tid + st]; d2[tid] += d2[tid + st]; }
        __syncthreads();
    }
    if (tid == 0) {
        double mu = d1[0] / 614400.0;
        double var = d2[0] / 614400.0 - mu * mu;
        g_mu[b] = (float)mu;
        g_rstd[b] = (float)(1.0 / sqrt(var + 1e-5));
    }
}

// ---------------- final layernorm ----------------
__global__ __launch_bounds__(256) void ln_kernel(float* __restrict__ out,
                                                 const float* __restrict__ lng,
                                                 const float* __restrict__ lnb) {
    size_t idx = (size_t)blockIdx.x * 256 + threadIdx.x;
    if (idx >= (size_t)SZ_X) return;
    int b = (int)(idx / 614400);
    int r = (int)(idx % 614400);
    out[idx] = (out[idx] - g_mu[b]) * g_rstd[b] * lng[r] + lnb[r];
}

// ---------------- copy S_coef / T_coef ----------------
__global__ __launch_bounds__(256) void copyout_kernel(float* __restrict__ out, int out_size) {
    if (out_size < SZ_TOTAL) return;
    size_t idx = (size_t)blockIdx.x * 256 + threadIdx.x;
    if (idx < (size_t)SZ_S) {
        out[OFF_S + idx] = g_Sscr[idx];
    } else if (idx < (size_t)(SZ_S + SZ_T)) {
        size_t t = idx - SZ_S;
        int b = (int)(t / 576);
        int rem = (int)(t % 576);
        int l = rem / 24, p = rem % 24;
        out[OFF_T + t] = g_T[b * 576 + p * 24 + l];
    }
}

// ---------------- launch ----------------
extern "C" void kernel_launch(void* const* d_in, const int* in_sizes, int n_in,
                              void* d_out, int out_size) {
    const float* x        = (const float*)d_in[0];
    const float* supports = (const float*)d_in[1];
    const float* conv1_w  = (const float*)d_in[2];
    const float* conv1_b  = (const float*)d_in[3];
    const float* t_cw1    = (const float*)d_in[4];
    const float* t_cw2    = (const float*)d_in[5];
    const float* t_w      = (const float*)d_in[6];
    const float* t_b      = (const float*)d_in[7];
    const float* t_v      = (const float*)d_in[8];
    const float* s_cw1    = (const float*)d_in[9];
    const float* s_cw2    = (const float*)d_in[10];
    const float* s_w      = (const float*)d_in[11];
    const float* s_b      = (const float*)d_in[12];
    const float* s_v      = (const float*)d_in[13];
    const float* g_w      = (const float*)d_in[14];
    const float* g_bv     = (const float*)d_in[15];
    const float* tc_w     = (const float*)d_in[16];
    const float* tc_b     = (const float*)d_in[17];
    const float* ln_g     = (const float*)d_in[18];
    const float* ln_b     = (const float*)d_in[19];
    float* out = (float*)d_out;

    cudaFuncSetAttribute(cheby_mma_kernel, cudaFuncAttributeMaxDynamicSharedMemorySize, CH_SMEM);
    cudaFuncSetAttribute(proj_mma_kernel, cudaFuncAttributeMaxDynamicSharedMemorySize, PJ_SMEM);
    cudaFuncSetAttribute(tc_mma_kernel, cudaFuncAttributeMaxDynamicSharedMemorySize, PJ_SMEM);

    // independent front-end passes
    featA_kernel<<<dim3(400, 64), 256>>>(x, t_cw1, s_cw1, s_cw2);
    f2t_kernel<<<dim3(64, 64), 192>>>(x, t_cw2);
    tatt_kernel<<<64, 256>>>(t_w, t_b, t_v);
    xta_kernel<<<dim3(400, 64), 64>>>(x);
    gs_kernel<<<dim3(400, 64), 64>>>(s_w);

    // spatial attention
    tile64_kernel<1><<<dim3(7, 7, 64), 256>>>(nullptr, s_b, 400, 400, 64);
    tile64_kernel<0><<<dim3(7, 7, 1), 256>>>(supports, nullptr, 400, 400, 400);
    tile64_kernel<2><<<dim3(7, 7, 64), 256>>>(s_v, nullptr, 400, 400, 400);
    colmax_kernel<<<64, 512>>>();
    smax_kernel<<<dim3(400, 64), 256>>>();

    // cheby (HMMA) + projection (HMMA, k=0 folded)
    cheby_mma_kernel<<<dim3(12, 4, 128), 256, CH_SMEM>>>(supports);
    proj_mma_kernel<<<dim3(50, 64), 256, PJ_SMEM>>>(g_w, g_bv);

    // temporal conv + conv1 residual fused (HMMA) + LN partials
    tc_mma_kernel<<<dim3(50, 64), 256, PJ_SMEM>>>(x, tc_w, tc_b, conv1_w, conv1_b, out);
    stats_kernel<<<64, 256>>>();
    ln_kernel<<<153600, 256>>>(out, ln_g, ln_b);

    // emit S_coef / T_coef
    copyout_kernel<<<(SZ_S + SZ_T + 255) / 256, 256>>>(out, out_size);
}

// round 11
// speedup vs baseline: 1.7072x; 1.0107x over previous
#include <cuda_runtime.h>
#include <cuda_bf16.h>
#include <math.h>
#include <stddef.h>
#include <stdint.h>

// Problem dims: B=64, C=64, CO=64, N=400, L=24, K=3, KT=3
// x layout [b,c,n,l]: idx = ((b*64+c)*400+n)*24+l
#define SZ_X      39321600
#define SZ_S      10240000
#define SZ_T      36864
#define OFF_S     39321600
#define OFF_T     49561600
#define SZ_TOTAL  49598464

// ---------------- scratch ----------------
__device__ float g_xta[SZ_X];            // x_TAt [b,n,c,l]
__device__ float g_Y[64*2*400*64*24];    // cheby k=1,2: [b,k-1,q, c*24+l]
__device__ float g_sg[SZ_X];
__device__ float g_f1t[64*24*400];
__device__ float g_f2t[64*64*24];
__device__ float g_f2s[64*64*400];
__device__ float g_gs[64*400*64];
__device__ float g_lsig[64*400*400];
__device__ float g_lg2s[64*400*400];
__device__ float g_Sscr[SZ_S];
__device__ float g_T[64*24*24];
__device__ float g_adj2[400*400];
__device__ float g_cmaxs[64*400];
__device__ float g_psum[64*50];
__device__ float g_psq[64*50];
__device__ float g_mu[64];
__device__ float g_rstd[64];

// ---------------- fused features + gs ----------------
// per (b,n): f1t[b,l,n], f2s[b,c,n], f1row (smem), gs[b,n,c] = f1row @ s_w
__global__ __launch_bounds__(256) void featA_kernel(const float* __restrict__ x,
                                                    const float* __restrict__ tcw1,
                                                    const float* __restrict__ scw1,
                                                    const float* __restrict__ scw2,
                                                    const float* __restrict__ sw) {
    int n = blockIdx.x, b = blockIdx.y;
    __shared__ float xs[1536];
    __shared__ float sws[1536];
    __shared__ float c1[64], c2[64], c3[24], f1sh[24];
    int tid = threadIdx.x;
    const float* xb = x + (size_t)b * 614400;
    for (int i = tid; i < 1536; i += 256) {
        int c = i / 24, l = i % 24;
        xs[i] = xb[c * 9600 + n * 24 + l];
        sws[i] = sw[i];
    }
    if (tid < 64) c1[tid] = tcw1[tid];
    else if (tid < 128) c2[tid - 64] = scw1[tid - 64];
    else if (tid < 152) c3[tid - 128] = scw2[tid - 128];
    __syncthreads();
    if (tid < 24) {
        int l = tid;
        float a1 = 0.f, a2 = 0.f;
        for (int c = 0; c < 64; c++) {
            float xv = xs[c * 24 + l];
            a1 += c1[c] * xv;
            a2 += c2[c] * xv;
        }
        g_f1t[(b * 24 + l) * 400 + n] = a1;
        f1sh[l] = a2;
    } else if (tid >= 64 && tid < 128) {
        int c = tid - 64;
        float a = 0.f;
        for (int l = 0; l < 24; l++) a += c3[l] * xs[c * 24 + l];
        g_f2s[(b * 64 + c) * 400 + n] = a;
    }
    __syncthreads();
    if (tid < 64) {
        float a = 0.f;
        for (int l = 0; l < 24; l++) a += f1sh[l] * sws[l * 64 + tid];
        g_gs[(b * 400 + n) * 64 + tid] = a;
    }
}

// ---------------- f2t ----------------
__global__ __launch_bounds__(192) void f2t_kernel(const float* __restrict__ x,
                                                  const float* __restrict__ tcw2) {
    int c = blockIdx.x, b = blockIdx.y;
    __shared__ float red[192];
    int tid = threadIdx.x;
    int l = tid % 24, g = tid / 24;
    const float* xb = x + (size_t)b * 614400 + c * 9600;
    float a = 0.f;
    for (int n = g; n < 400; n += 8) a += tcw2[n] * xb[n * 24 + l];
    red[tid] = a;
    __syncthreads();
    if (tid < 24) {
        float s = 0.f;
        for (int gg = 0; gg < 8; gg++) s += red[gg * 24 + tid];
        g_f2t[(b * 64 + c) * 24 + tid] = s;
    }
}

// ---------------- temporal attention ----------------
__global__ __launch_bounds__(256) void tatt_kernel(const float* __restrict__ tw,
                                                   const float* __restrict__ tb,
                                                   const float* __restrict__ tv) {
    int b = blockIdx.x;
    __shared__ float f1tile[24 * 64], twtile[64 * 64], f2ts[64 * 24], gt[24 * 64];
    __shared__ float lg[576], lg2[576], cmax[24], rsum[24];
    int tid = threadIdx.x;
    for (int i = tid; i < 1536; i += 256) f2ts[i] = g_f2t[b * 1536 + i];

    int pg = tid >> 6;
    int c  = tid & 63;
    float acc[6] = {0.f, 0.f, 0.f, 0.f, 0.f, 0.f};
    for (int n0 = 0; n0 < 400; n0 += 64) {
        __syncthreads();
        for (int i = tid; i < 1536; i += 256) {
            int p = i >> 6, nn = i & 63;
            f1tile[i] = (n0 + nn < 400) ? g_f1t[(b * 24 + p) * 400 + n0 + nn] : 0.f;
        }
        for (int i = tid; i < 4096; i += 256) {
            int nn = i >> 6, cc = i & 63;
            twtile[i] = (n0 + nn < 400) ? tw[(n0 + nn) * 64 + cc] : 0.f;
        }
        __syncthreads();
        for (int nn = 0; nn < 64; nn++) {
            float wv = twtile[nn * 64 + c];
#pragma unroll
            for (int j = 0; j < 6; j++) acc[j] += f1tile[(pg * 6 + j) * 64 + nn] * wv;
        }
    }
    __syncthreads();
#pragma unroll
    for (int j = 0; j < 6; j++) gt[(pg * 6 + j) * 64 + c] = acc[j];
    __syncthreads();
    for (int i = tid; i < 576; i += 256) {
        int p = i / 24, l = i % 24;
        float s = tb[i];
        for (int cc = 0; cc < 64; cc++) s += gt[p * 64 + cc] * f2ts[cc * 24 + l];
        lg[i] = 1.f / (1.f + expf(-s));
    }
    __syncthreads();
    for (int i = tid; i < 576; i += 256) {
        int p = i / 24, l = i % 24;
        float s = 0.f;
        for (int q = 0; q < 24; q++) s += tv[p * 24 + q] * lg[q * 24 + l];
        lg2[i] = s;
    }
    __syncthreads();
    if (tid < 24) {
        float m = -1e30f;
        for (int p = 0; p < 24; p++) m = fmaxf(m, lg2[p * 24 + tid]);
        cmax[tid] = m;
    }
    __syncthreads();
    for (int i = tid; i < 576; i += 256) {
        int l = i % 24;
        lg[i] = expf(lg2[i] - cmax[l]);
    }
    __syncthreads();
    if (tid < 24) {
        float s = 0.f;
        for (int l = 0; l < 24; l++) s += lg[tid * 24 + l];
        rsum[tid] = s;
    }
    __syncthreads();
    for (int i = tid; i < 576; i += 256) {
        int p = i / 24;
        g_T[b * 576 + i] = lg[i] / rsum[p];
    }
}

// ---------------- x_TAt (float2-vectorized) ----------------
__global__ __launch_bounds__(64) void xta_kernel(const float* __restrict__ x) {
    int n = blockIdx.x, b = blockIdx.y;
    __shared__ float xs[1536], Ts[576];
    int tid = threadIdx.x;
    const float* xb = x + (size_t)b * 614400;
    // stage x (float4): row c is 24 consecutive floats = 6 float4
    for (int i = tid; i < 384; i += 64) {
        int c = i / 6, v = i % 6;
        ((float4*)xs)[i] = *(const float4*)(xb + (size_t)c * 9600 + n * 24 + v * 4);
    }
    for (int i = tid; i < 144; i += 64)
        ((float4*)Ts)[i] = *(const float4*)(g_T + b * 576 + i * 4);
    __syncthreads();
    int cg = (tid >> 2) * 4, qg = (tid & 3) * 6;
    float acc[4][6] = {};
#pragma unroll
    for (int l2 = 0; l2 < 12; l2++) {
        float2 tv2[6];
#pragma unroll
        for (int j = 0; j < 6; j++) tv2[j] = *(const float2*)&Ts[(qg + j) * 24 + l2 * 2];
#pragma unroll
        for (int i = 0; i < 4; i++) {
            float2 xv = *(const float2*)&xs[(cg + i) * 24 + l2 * 2];
#pragma unroll
            for (int j = 0; j < 6; j++)
                acc[i][j] += xv.x * tv2[j].x + xv.y * tv2[j].y;
        }
    }
    float* o = g_xta + ((size_t)(b * 400 + n)) * 1536;
#pragma unroll
    for (int i = 0; i < 4; i++)
#pragma unroll
        for (int j = 0; j < 6; j++) o[(cg + i) * 24 + qg + j] = acc[i][j];
}

// ---------------- generic 64x64-tile SGEMM ----------------
// MODE 0: g_adj2 = A @ A ; MODE 1: lsig = sigmoid(gs@f2s + s_b)
template <int MODE>
__global__ __launch_bounds__(256) void tile64_kernel(const float* __restrict__ Aext,
                                                     const float* __restrict__ biasext,
                                                     int M, int N, int Kd) {
    int zb = blockIdx.z;
    const float* A;
    const float* Bm;
    float* C;
    if (MODE == 0) { A = Aext; Bm = Aext; C = g_adj2; }
    else { A = g_gs + (size_t)zb * 25600; Bm = g_f2s + (size_t)zb * 25600; C = g_lsig + (size_t)zb * 160000; }

    int m0 = blockIdx.y * 64, n0 = blockIdx.x * 64;
    __shared__ float As[16][68], Bs[16][68];
    int tid = threadIdx.x;
    int tx = tid & 15, ty = tid >> 4;
    float acc[4][4] = {};
    for (int k0 = 0; k0 < Kd; k0 += 16) {
#pragma unroll
        for (int r = 0; r < 4; r++) {
            int lin = tid + 256 * r;
            int kk = lin & 15, m = lin >> 4;
            float v = 0.f;
            if (m0 + m < M && k0 + kk < Kd) v = A[(size_t)(m0 + m) * Kd + k0 + kk];
            As[kk][m] = v;
            int j = lin & 63, kk2 = lin >> 6;
            float v2 = 0.f;
            if (k0 + kk2 < Kd && n0 + j < N) v2 = Bm[(size_t)(k0 + kk2) * N + n0 + j];
            Bs[kk2][j] = v2;
        }
        __syncthreads();
#pragma unroll
        for (int kk = 0; kk < 16; kk++) {
            float a[4], bb[4];
#pragma unroll
            for (int i = 0; i < 4; i++) a[i] = As[kk][ty * 4 + i];
#pragma unroll
            for (int j = 0; j < 4; j++) bb[j] = Bs[kk][tx * 4 + j];
#pragma unroll
            for (int i = 0; i < 4; i++)
#pragma unroll
                for (int j = 0; j < 4; j++) acc[i][j] += a[i] * bb[j];
        }
        __syncthreads();
    }
#pragma unroll
    for (int i = 0; i < 4; i++) {
        int m = m0 + ty * 4 + i;
        if (m >= M) break;
#pragma unroll
        for (int j = 0; j < 4; j++) {
            int nn = n0 + tx * 4 + j;
            if (nn >= N) continue;
            float v = acc[i][j];
            if (MODE == 1) v = 1.f / (1.f + expf(-(v + biasext[(size_t)m * N + nn])));
            C[(size_t)m * N + nn] = v;
        }
    }
}

// ---------------- column max / softmax ----------------
__global__ __launch_bounds__(512) void colmax_kernel() {
    int b = blockIdx.x;
    int tid = threadIdx.x;
    if (tid < 400) {
        const float* base = g_lg2s + (size_t)b * 160000 + tid;
        float m = -1e30f;
        for (int p = 0; p < 400; p++) m = fmaxf(m, base[p * 400]);
        g_cmaxs[b * 400 + tid] = m;
    }
}

__global__ __launch_bounds__(256) void smax_kernel() {
    int p = blockIdx.x, b = blockIdx.y;
    int tid = threadIdx.x;
    __shared__ float red[256];
    const float* row = g_lg2s + (size_t)b * 160000 + p * 400;
    const float* cm = g_cmaxs + b * 400;
    float* orow = g_Sscr + (size_t)b * 160000 + p * 400;
    float s = 0.f;
    for (int n = tid; n < 400; n += 256) {
        float e = expf(row[n] - cm[n]);
        orow[n] = e;
        s += e;
    }
    red[tid] = s;
    __syncthreads();
    for (int st = 128; st > 0; st >>= 1) {
        if (tid < st) red[tid] += red[tid + st];
        __syncthreads();
    }
    float inv = 1.f / red[0];
    for (int n = tid; n < 400; n += 256) orow[n] *= inv;
}

// ---------------- HMMA helper ----------------
__device__ __forceinline__ void mma16816(float* d, const uint32_t* a, const uint32_t* b) {
    asm volatile(
        "mma.sync.aligned.m16n8k16.row.col.f32.bf16.bf16.f32 "
        "{%0,%1,%2,%3}, {%4,%5,%6,%7}, {%8,%9}, {%0,%1,%2,%3};"
        : "+f"(d[0]), "+f"(d[1]), "+f"(d[2]), "+f"(d[3])
        : "r"(a[0]), "r"(a[1]), "r"(a[2]), "r"(a[3]), "r"(b[0]), "r"(b[1]));
}

// ======================================================================
// cheby via warp-level mma.sync (HMMA bf16, fp32 accum, hi/lo compensation)
// ======================================================================
#define CH_LDK 72
#define CH_ASZ (128 * CH_LDK)
#define CH_SMEM (4 * CH_ASZ * 2)

__global__ __launch_bounds__(256) void cheby_mma_kernel(const float* __restrict__ adj) {
    extern __shared__ char chsm[];
    __nv_bfloat16* As_hi = (__nv_bfloat16*)chsm;
    __nv_bfloat16* As_lo = As_hi + CH_ASZ;
    __nv_bfloat16* Bs_hi = As_lo + CH_ASZ;
    __nv_bfloat16* Bs_lo = Bs_hi + CH_ASZ;

    int tid = threadIdx.x;
    int wid = tid >> 5, lane = tid & 31;
    int g = lane >> 2, tg = lane & 3;
    int b = blockIdx.z >> 1;
    int kvar = blockIdx.z & 1;
    int q0 = blockIdx.y * 128;
    int j0 = blockIdx.x * 128;
    const float* Sb = g_Sscr + (size_t)b * 160000;
    const float* Xb = g_xta + (size_t)b * 614400;
    int m_off = (wid >> 2) * 64;
    int n_off = (wid & 3) * 32;

    float acc[4][4][4];
#pragma unroll
    for (int im = 0; im < 4; im++)
#pragma unroll
        for (int in_ = 0; in_ < 4; in_++)
#pragma unroll
            for (int r = 0; r < 4; r++) acc[im][in_][r] = 0.f;

    for (int ch = 0; ch < 7; ch++) {
        int n0k = ch * 64;
#pragma unroll 4
        for (int i = 0; i < 32; i++) {
            int lin = tid + 256 * i;
            int kk = lin & 63, q = lin >> 6;
            int gq = q0 + q, gn = n0k + kk;
            float a = 0.f;
            if (gq < 400 && gn < 400) {
                float s = Sb[gq * 400 + gn];
                if (kvar == 0) a = s * adj[gq * 400 + gn];
                else a = s * (2.f * g_adj2[gq * 400 + gn] - (gq == gn ? 1.f : 0.f));
            }
            __nv_bfloat16 h = __float2bfloat16(a);
            __nv_bfloat16 l = __float2bfloat16(a - __bfloat162float(h));
            As_hi[q * CH_LDK + kk] = h;
            As_lo[q * CH_LDK + kk] = l;
        }
#pragma unroll 4
        for (int i = 0; i < 32; i++) {
            int lin = tid + 256 * i;
            int j = lin & 127, kk = lin >> 7;
            int gn = n0k + kk;
            float v = (gn < 400) ? Xb[(size_t)gn * 1536 + j0 + j] : 0.f;
            __nv_bfloat16 h = __float2bfloat16(v);
            __nv_bfloat16 l = __float2bfloat16(v - __bfloat162float(h));
            Bs_hi[j * CH_LDK + kk] = h;
            Bs_lo[j * CH_LDK + kk] = l;
        }
        __syncthreads();
#pragma unroll
        for (int ks = 0; ks < 4; ks++) {
            int kb = ks * 16;
            uint32_t ah[4][4], al[4][4], bh[4][2], bl[4][2];
#pragma unroll
            for (int im = 0; im < 4; im++) {
                int r0 = m_off + im * 16 + g;
                int cA = kb + tg * 2;
                ah[im][0] = *(const uint32_t*)&As_hi[r0 * CH_LDK + cA];
                ah[im][1] = *(const uint32_t*)&As_hi[(r0 + 8) * CH_LDK + cA];
                ah[im][2] = *(const uint32_t*)&As_hi[r0 * CH_LDK + cA + 8];
                ah[im][3] = *(const uint32_t*)&As_hi[(r0 + 8) * CH_LDK + cA + 8];
                al[im][0] = *(const uint32_t*)&As_lo[r0 * CH_LDK + cA];
                al[im][1] = *(const uint32_t*)&As_lo[(r0 + 8) * CH_LDK + cA];
                al[im][2] = *(const uint32_t*)&As_lo[r0 * CH_LDK + cA + 8];
                al[im][3] = *(const uint32_t*)&As_lo[(r0 + 8) * CH_LDK + cA + 8];
            }
#pragma unroll
            for (int in_ = 0; in_ < 4; in_++) {
                int col = n_off + in_ * 8 + g;
                int rB = kb + tg * 2;
                bh[in_][0] = *(const uint32_t*)&Bs_hi[col * CH_LDK + rB];
                bh[in_][1] = *(const uint32_t*)&Bs_hi[col * CH_LDK + rB + 8];
                bl[in_][0] = *(const uint32_t*)&Bs_lo[col * CH_LDK + rB];
                bl[in_][1] = *(const uint32_t*)&Bs_lo[col * CH_LDK + rB + 8];
            }
#pragma unroll
            for (int im = 0; im < 4; im++)
#pragma unroll
                for (int in_ = 0; in_ < 4; in_++) {
                    mma16816(acc[im][in_], ah[im], bh[in_]);
                    mma16816(acc[im][in_], ah[im], bl[in_]);
                    mma16816(acc[im][in_], al[im], bh[in_]);
                }
        }
        __syncthreads();
    }

    float* Yb = g_Y + (size_t)(b * 2 + kvar) * 614400;
#pragma unroll
    for (int im = 0; im < 4; im++) {
        int r0 = q0 + m_off + im * 16 + g;
#pragma unroll
        for (int in_ = 0; in_ < 4; in_++) {
            int col = j0 + n_off + in_ * 8 + tg * 2;
            if (r0 < 400) {
                float2 v = make_float2(acc[im][in_][0], acc[im][in_][1]);
                *(float2*)&Yb[(size_t)r0 * 1536 + col] = v;
            }
            if (r0 + 8 < 400) {
                float2 v = make_float2(acc[im][in_][2], acc[im][in_][3]);
                *(float2*)&Yb[(size_t)(r0 + 8) * 1536 + col] = v;
            }
        }
    }
}

// ======================================================================
// s_v @ lsig via HMMA: lg2s[b,p,n] = sum_q s_v[p,q]*lsig[b,q,n]
// M=N=K=400; grid (4 n-blk, 4 p-blk, 64 b); same structure as cheby.
// ======================================================================
__global__ __launch_bounds__(256) void sv_mma_kernel(const float* __restrict__ sv) {
    extern __shared__ char svsm[];
    __nv_bfloat16* As_hi = (__nv_bfloat16*)svsm;
    __nv_bfloat16* As_lo = As_hi + CH_ASZ;
    __nv_bfloat16* Bs_hi = As_lo + CH_ASZ;
    __nv_bfloat16* Bs_lo = Bs_hi + CH_ASZ;

    int tid = threadIdx.x;
    int wid = tid >> 5, lane = tid & 31;
    int g = lane >> 2, tg = lane & 3;
    int b = blockIdx.z;
    int p0 = blockIdx.y * 128;
    int j0 = blockIdx.x * 128;
    const float* Lb = g_lsig + (size_t)b * 160000;
    int m_off = (wid >> 2) * 64;
    int n_off = (wid & 3) * 32;

    float acc[4][4][4];
#pragma unroll
    for (int im = 0; im < 4; im++)
#pragma unroll
        for (int in_ = 0; in_ < 4; in_++)
#pragma unroll
            for (int r = 0; r < 4; r++) acc[im][in_][r] = 0.f;

    for (int ch = 0; ch < 7; ch++) {
        int n0k = ch * 64;
#pragma unroll 4
        for (int i = 0; i < 32; i++) {
            int lin = tid + 256 * i;
            int kk = lin & 63, p = lin >> 6;
            int gp = p0 + p, gq = n0k + kk;
            float a = 0.f;
            if (gp < 400 && gq < 400) a = sv[gp * 400 + gq];
            __nv_bfloat16 h = __float2bfloat16(a);
            __nv_bfloat16 l = __float2bfloat16(a - __bfloat162float(h));
            As_hi[p * CH_LDK + kk] = h;
            As_lo[p * CH_LDK + kk] = l;
        }
#pragma unroll 4
        for (int i = 0; i < 32; i++) {
            int lin = tid + 256 * i;
            int j = lin & 127, kk = lin >> 7;
            int gq = n0k + kk, gn = j0 + j;
            float v = (gq < 400 && gn < 400) ? Lb[(size_t)gq * 400 + gn] : 0.f;
            __nv_bfloat16 h = __float2bfloat16(v);
            __nv_bfloat16 l = __float2bfloat16(v - __bfloat162float(h));
            Bs_hi[j * CH_LDK + kk] = h;
            Bs_lo[j * CH_LDK + kk] = l;
        }
        __syncthreads();
#pragma unroll
        for (int ks = 0; ks < 4; ks++) {
            int kb = ks * 16;
            uint32_t ah[4][4], al[4][4], bh[4][2], bl[4][2];
#pragma unroll
            for (int im = 0; im < 4; im++) {
                int r0 = m_off + im * 16 + g;
                int cA = kb + tg * 2;
                ah[im][0] = *(const uint32_t*)&As_hi[r0 * CH_LDK + cA];
                ah[im][1] = *(const uint32_t*)&As_hi[(r0 + 8) * CH_LDK + cA];
                ah[im][2] = *(const uint32_t*)&As_hi[r0 * CH_LDK + cA + 8];
                ah[im][3] = *(const uint32_t*)&As_hi[(r0 + 8) * CH_LDK + cA + 8];
                al[im][0] = *(const uint32_t*)&As_lo[r0 * CH_LDK + cA];
                al[im][1] = *(const uint32_t*)&As_lo[(r0 + 8) * CH_LDK + cA];
                al[im][2] = *(const uint32_t*)&As_lo[r0 * CH_LDK + cA + 8];
                al[im][3] = *(const uint32_t*)&As_lo[(r0 + 8) * CH_LDK + cA + 8];
            }
#pragma unroll
            for (int in_ = 0; in_ < 4; in_++) {
                int col = n_off + in_ * 8 + g;
                int rB = kb + tg * 2;
                bh[in_][0] = *(const uint32_t*)&Bs_hi[col * CH_LDK + rB];
                bh[in_][1] = *(const uint32_t*)&Bs_hi[col * CH_LDK + rB + 8];
                bl[in_][0] = *(const uint32_t*)&Bs_lo[col * CH_LDK + rB];
                bl[in_][1] = *(const uint32_t*)&Bs_lo[col * CH_LDK + rB + 8];
            }
#pragma unroll
            for (int im = 0; im < 4; im++)
#pragma unroll
                for (int in_ = 0; in_ < 4; in_++) {
                    mma16816(acc[im][in_], ah[im], bh[in_]);
                    mma16816(acc[im][in_], ah[im], bl[in_]);
                    mma16816(acc[im][in_], al[im], bh[in_]);
                }
        }
        __syncthreads();
    }

    float* Cb = g_lg2s + (size_t)b * 160000;
#pragma unroll
    for (int im = 0; im < 4; im++) {
        int r0 = p0 + m_off + im * 16 + g;
#pragma unroll
        for (int in_ = 0; in_ < 4; in_++) {
            int col = j0 + n_off + in_ * 8 + tg * 2;
            if (col < 400) {
                if (r0 < 400)
                    *(float2*)&Cb[(size_t)r0 * 400 + col] =
                        make_float2(acc[im][in_][0], acc[im][in_][1]);
                if (r0 + 8 < 400)
                    *(float2*)&Cb[(size_t)(r0 + 8) * 400 + col] =
                        make_float2(acc[im][in_][2], acc[im][in_][3]);
            }
        }
    }
}

// ======================================================================
// proj via HMMA:  sg[b,o,q,l] = relu(W[64x192] @ Y[192x(q,l)] + gb[o])
// ======================================================================
#define PJ_LDA 66
#define PJ_ASZ (64 * PJ_LDA)     // 4224
#define PJ_BSZ (192 * PJ_LDA)    // 12672
#define PJ_SMEM ((2 * PJ_ASZ + 2 * PJ_BSZ) * 2)  // 67584 bytes

__global__ __launch_bounds__(256) void proj_mma_kernel(const float* __restrict__ gw,
                                                       const float* __restrict__ gb) {
    extern __shared__ char pjsm[];
    __nv_bfloat16* Ah = (__nv_bfloat16*)pjsm;
    __nv_bfloat16* Al = Ah + PJ_ASZ;
    __nv_bfloat16* Bh = Al + PJ_ASZ;
    __nv_bfloat16* Bl = Bh + PJ_BSZ;
    __shared__ float sqq[8];
    int tid = threadIdx.x;
    int wid = tid >> 5, lane = tid & 31;
    int g = lane >> 2, tg = lane & 3;
    int b = blockIdx.y, q0 = blockIdx.x * 8;
    if (tid < 8) sqq[tid] = g_Sscr[(size_t)b * 160000 + (size_t)(q0 + tid) * 401];
    __syncthreads();

    float acc[4][3][4];
#pragma unroll
    for (int mf = 0; mf < 4; mf++)
#pragma unroll
        for (int nf = 0; nf < 3; nf++)
#pragma unroll
            for (int r = 0; r < 4; r++) acc[mf][nf][r] = 0.f;

    for (int k = 0; k < 3; k++) {
        for (int i = tid; i < 4096; i += 256) {
            int o = i >> 6, c = i & 63;
            float v = gw[o * 192 + c * 3 + k];
            __nv_bfloat16 h = __float2bfloat16(v);
            Ah[o * PJ_LDA + c] = h;
            Al[o * PJ_LDA + c] = __float2bfloat16(v - __bfloat162float(h));
        }
#pragma unroll 4
        for (int i = 0; i < 48; i++) {
            int lin = tid + 256 * i;
            int q = lin / 1536;
            int rem = lin - q * 1536;
            int c = rem / 24, l = rem - c * 24;
            float v;
            if (k == 0)
                v = sqq[q] * g_xta[((size_t)(b * 400 + q0 + q)) * 1536 + c * 24 + l];
            else
                v = g_Y[((size_t)(b * 2 + (k - 1)) * 400 + q0 + q) * 1536 + c * 24 + l];
            __nv_bfloat16 h = __float2bfloat16(v);
            int col = q * 24 + l;
            Bh[col * PJ_LDA + c] = h;
            Bl[col * PJ_LDA + c] = __float2bfloat16(v - __bfloat162float(h));
        }
        __syncthreads();
#pragma unroll
        for (int ks = 0; ks < 4; ks++) {
            int kb = ks * 16;
            uint32_t ah[4][4], al[4][4], bh[3][2], bl[3][2];
#pragma unroll
            for (int mf = 0; mf < 4; mf++) {
                int r0 = mf * 16 + g;
                int cA = kb + tg * 2;
                ah[mf][0] = *(const uint32_t*)&Ah[r0 * PJ_LDA + cA];
                ah[mf][1] = *(const uint32_t*)&Ah[(r0 + 8) * PJ_LDA + cA];
                ah[mf][2] = *(const uint32_t*)&Ah[r0 * PJ_LDA + cA + 8];
                ah[mf][3] = *(const uint32_t*)&Ah[(r0 + 8) * PJ_LDA + cA + 8];
                al[mf][0] = *(const uint32_t*)&Al[r0 * PJ_LDA + cA];
                al[mf][1] = *(const uint32_t*)&Al[(r0 + 8) * PJ_LDA + cA];
                al[mf][2] = *(const uint32_t*)&Al[r0 * PJ_LDA + cA + 8];
                al[mf][3] = *(const uint32_t*)&Al[(r0 + 8) * PJ_LDA + cA + 8];
            }
#pragma unroll
            for (int nf = 0; nf < 3; nf++) {
                int col = wid * 24 + nf * 8 + g;
                int rB = kb + tg * 2;
                bh[nf][0] = *(const uint32_t*)&Bh[col * PJ_LDA + rB];
                bh[nf][1] = *(const uint32_t*)&Bh[col * PJ_LDA + rB + 8];
                bl[nf][0] = *(const uint32_t*)&Bl[col * PJ_LDA + rB];
                bl[nf][1] = *(const uint32_t*)&Bl[col * PJ_LDA + rB + 8];
            }
#pragma unroll
            for (int mf = 0; mf < 4; mf++)
#pragma unroll
                for (int nf = 0; nf < 3; nf++) {
                    mma16816(acc[mf][nf], ah[mf], bh[nf]);
                    mma16816(acc[mf][nf], ah[mf], bl[nf]);
                    mma16816(acc[mf][nf], al[mf], bh[nf]);
                }
        }
        __syncthreads();
    }

    int q = q0 + wid;
#pragma unroll
    for (int mf = 0; mf < 4; mf++) {
        int o0 = mf * 16 + g;
        float b0 = gb[o0], b1 = gb[o0 + 8];
#pragma unroll
        for (int nf = 0; nf < 3; nf++) {
            int l = nf * 8 + tg * 2;
            float2 v0 = make_float2(fmaxf(acc[mf][nf][0] + b0, 0.f),
                                    fmaxf(acc[mf][nf][1] + b0, 0.f));
            *(float2*)&g_sg[(size_t)(b * 64 + o0) * 9600 + q * 24 + l] = v0;
            float2 v1 = make_float2(fmaxf(acc[mf][nf][2] + b1, 0.f),
                                    fmaxf(acc[mf][nf][3] + b1, 0.f));
            *(float2*)&g_sg[(size_t)(b * 64 + o0 + 8) * 9600 + q * 24 + l] = v1;
        }
    }
}

// ======================================================================
// temporal conv + residual (conv1 fused as 4th K chunk) via HMMA
// ======================================================================
__global__ __launch_bounds__(256) void tc_mma_kernel(const float* __restrict__ x,
                                                     const float* __restrict__ tcw,
                                                     const float* __restrict__ tcb,
                                                     const float* __restrict__ c1w,
                                                     const float* __restrict__ c1b,
                                                     float* __restrict__ hout) {
    extern __shared__ char tcsm[];
    __nv_bfloat16* Ah = (__nv_bfloat16*)tcsm;
    __nv_bfloat16* Al = Ah + PJ_ASZ;
    __nv_bfloat16* Bh = Al + PJ_ASZ;
    __nv_bfloat16* Bl = Bh + PJ_BSZ;
    __shared__ float r1[256], r2[256];
    int tid = threadIdx.x;
    int wid = tid >> 5, lane = tid & 31;
    int g = lane >> 2, tg = lane & 3;
    int b = blockIdx.y, n0 = blockIdx.x * 8;

    float acc[4][3][4];
#pragma unroll
    for (int mf = 0; mf < 4; mf++)
#pragma unroll
        for (int nf = 0; nf < 3; nf++)
#pragma unroll
            for (int r = 0; r < 4; r++) acc[mf][nf][r] = 0.f;

    for (int kc = 0; kc < 4; kc++) {
        for (int i = tid; i < 4096; i += 256) {
            int o = i >> 6, c = i & 63;
            float v = (kc < 3) ? tcw[o * 192 + c * 3 + kc] : c1w[o * 64 + c];
            __nv_bfloat16 h = __float2bfloat16(v);
            Ah[o * PJ_LDA + c] = h;
            Al[o * PJ_LDA + c] = __float2bfloat16(v - __bfloat162float(h));
        }
#pragma unroll 4
        for (int i = 0; i < 48; i++) {
            int lin = tid + 256 * i;
            int q = lin / 1536;
            int rem = lin - q * 1536;
            int c = rem / 24, l = rem - c * 24;
            float v;
            if (kc < 3) {
                int ls = l + kc - 1;
                v = (ls >= 0 && ls < 24)
                        ? g_sg[(size_t)(b * 64 + c) * 9600 + (n0 + q) * 24 + ls]
                        : 0.f;
            } else {
                v = x[((size_t)(b * 64 + c) * 400 + n0 + q) * 24 + l];
            }
            __nv_bfloat16 h = __float2bfloat16(v);
            int col = q * 24 + l;
            Bh[col * PJ_LDA + c] = h;
            Bl[col * PJ_LDA + c] = __float2bfloat16(v - __bfloat162float(h));
        }
        __syncthreads();
#pragma unroll
        for (int ks = 0; ks < 4; ks++) {
            int kb = ks * 16;
            uint32_t ah[4][4], al[4][4], bh[3][2], bl[3][2];
#pragma unroll
            for (int mf = 0; mf < 4; mf++) {
                int r0 = mf * 16 + g;
                int cA = kb + tg * 2;
                ah[mf][0] = *(const uint32_t*)&Ah[r0 * PJ_LDA + cA];
                ah[mf][1] = *(const uint32_t*)&Ah[(r0 + 8) * PJ_LDA + cA];
                ah[mf][2] = *(const uint32_t*)&Ah[r0 * PJ_LDA + cA + 8];
                ah[mf][3] = *(const uint32_t*)&Ah[(r0 + 8) * PJ_LDA + cA + 8];
                al[mf][0] = *(const uint32_t*)&Al[r0 * PJ_LDA + cA];
                al[mf][1] = *(const uint32_t*)&Al[(r0 + 8) * PJ_LDA + cA];
                al[mf][2] = *(const uint32_t*)&Al[r0 * PJ_LDA + cA + 8];
                al[mf][3] = *(const uint32_t*)&Al[(r0 + 8) * PJ_LDA + cA + 8];
            }
#pragma unroll
            for (int nf = 0; nf < 3; nf++) {
                int col = wid * 24 + nf * 8 + g;
                int rB = kb + tg * 2;
                bh[nf][0] = *(const uint32_t*)&Bh[col * PJ_LDA + rB];
                bh[nf][1] = *(const uint32_t*)&Bh[col * PJ_LDA + rB + 8];
                bl[nf][0] = *(const uint32_t*)&Bl[col * PJ_LDA + rB];
                bl[nf][1] = *(const uint32_t*)&Bl[col * PJ_LDA + rB + 8];
            }
#pragma unroll
            for (int mf = 0; mf < 4; mf++)
#pragma unroll
                for (int nf = 0; nf < 3; nf++) {
                    mma16816(acc[mf][nf], ah[mf], bh[nf]);
                    mma16816(acc[mf][nf], ah[mf], bl[nf]);
                    mma16816(acc[mf][nf], al[mf], bh[nf]);
                }
        }
        __syncthreads();
    }

    int n = n0 + wid;
    float s = 0.f, ss = 0.f;
#pragma unroll
    for (int mf = 0; mf < 4; mf++) {
        int o0 = mf * 16 + g;
        float b0 = tcb[o0] + c1b[o0];
        float b1 = tcb[o0 + 8] + c1b[o0 + 8];
#pragma unroll
        for (int nf = 0; nf < 3; nf++) {
            int l = nf * 8 + tg * 2;
            float h0 = fmaxf(acc[mf][nf][0] + b0, 0.f);
            float h1 = fmaxf(acc[mf][nf][1] + b0, 0.f);
            float h2 = fmaxf(acc[mf][nf][2] + b1, 0.f);
            float h3 = fmaxf(acc[mf][nf][3] + b1, 0.f);
            *(float2*)&hout[(size_t)(b * 64 + o0) * 9600 + n * 24 + l] = make_float2(h0, h1);
            *(float2*)&hout[(size_t)(b * 64 + o0 + 8) * 9600 + n * 24 + l] = make_float2(h2, h3);
            s += h0 + h1 + h2 + h3;
            ss += h0 * h0 + h1 * h1 + h2 * h2 + h3 * h3;
        }
    }
    r1[tid] = s; r2[tid] = ss;
    __syncthreads();
    for (int st = 128; st > 0; st >>= 1) {
        if (tid < st) { r1[tid] += r1[tid + st]; r2[tid] += r2[tid + st]; }
        __syncthreads();
    }
    if (tid == 0) {
        g_psum[b * 50 + blockIdx.x] = r1[0];
        g_psq[b * 50 + blockIdx.x] = r2[0];
    }
}

// ---------------- per-batch stats ----------------
__global__ __launch_bounds__(256) void stats_kernel() {
    int b = blockIdx.x;
    int tid = threadIdx.x;
    __shared__ double d1[256], d2[256];
    double s = 0.0, ss = 0.0;
    for (int i = tid; i < 50; i += 256) { s += (double)g_psum[b * 50 + i]; ss += (double)g_psq[b * 50 + i]; }
    d1[tid] = s; d2[tid] = ss;
    __syncthreads();
    for (int st = 128; st > 0; st >>= 1) {
        if (tid < st) { d1[tid] += d1[tid + st]; d2[tid] += d2[tid + st]; }
        __syncthreads();
    }
    if (tid == 0) {
        double mu = d1[0] / 614400.0;
        double var = d2[0] / 614400.0 - mu * mu;
        g_mu[b] = (float)mu;
        g_rstd[b] = (float)(1.0 / sqrt(var + 1e-5));
    }
}

// ---------------- final layernorm ----------------
__global__ __launch_bounds__(256) void ln_kernel(float* __restrict__ out,
                                                 const float* __restrict__ lng,
                                                 const float* __restrict__ lnb) {
    size_t idx = (size_t)blockIdx.x * 256 + threadIdx.x;
    if (idx >= (size_t)SZ_X) return;
    int b = (int)(idx / 614400);
    int r = (int)(idx % 614400);
    out[idx] = (out[idx] - g_mu[b]) * g_rstd[b] * lng[r] + lnb[r];
}

// ---------------- copy S_coef / T_coef ----------------
__global__ __launch_bounds__(256) void copyout_kernel(float* __restrict__ out, int out_size) {
    if (out_size < SZ_TOTAL) return;
    size_t idx = (size_t)blockIdx.x * 256 + threadIdx.x;
    if (idx < (size_t)SZ_S) {
        out[OFF_S + idx] = g_Sscr[idx];
    } else if (idx < (size_t)(SZ_S + SZ_T)) {
        size_t t = idx - SZ_S;
        int b = (int)(t / 576);
        int rem = (int)(t % 576);
        int l = rem / 24, p = rem % 24;
        out[OFF_T + t] = g_T[b * 576 + p * 24 + l];
    }
}

// ---------------- launch ----------------
extern "C" void kernel_launch(void* const* d_in, const int* in_sizes, int n_in,
                              void* d_out, int out_size) {
    const float* x        = (const float*)d_in[0];
    const float* supports = (const float*)d_in[1];
    const float* conv1_w  = (const float*)d_in[2];
    const float* conv1_b  = (const float*)d_in[3];
    const float* t_cw1    = (const float*)d_in[4];
    const float* t_cw2    = (const float*)d_in[5];
    const float* t_w      = (const float*)d_in[6];
    const float* t_b      = (const float*)d_in[7];
    const float* t_v      = (const float*)d_in[8];
    const float* s_cw1    = (const float*)d_in[9];
    const float* s_cw2    = (const float*)d_in[10];
    const float* s_w      = (const float*)d_in[11];
    const float* s_b      = (const float*)d_in[12];
    const float* s_v      = (const float*)d_in[13];
    const float* g_w      = (const float*)d_in[14];
    const float* g_bv     = (const float*)d_in[15];
    const float* tc_w     = (const float*)d_in[16];
    const float* tc_b     = (const float*)d_in[17];
    const float* ln_g     = (const float*)d_in[18];
    const float* ln_b     = (const float*)d_in[19];
    float* out = (float*)d_out;

    cudaFuncSetAttribute(cheby_mma_kernel, cudaFuncAttributeMaxDynamicSharedMemorySize, CH_SMEM);
    cudaFuncSetAttribute(sv_mma_kernel, cudaFuncAttributeMaxDynamicSharedMemorySize, CH_SMEM);
    cudaFuncSetAttribute(proj_mma_kernel, cudaFuncAttributeMaxDynamicSharedMemorySize, PJ_SMEM);
    cudaFuncSetAttribute(tc_mma_kernel, cudaFuncAttributeMaxDynamicSharedMemorySize, PJ_SMEM);

    // independent front-end passes (gs fused into featA)
    featA_kernel<<<dim3(400, 64), 256>>>(x, t_cw1, s_cw1, s_cw2, s_w);
    f2t_kernel<<<dim3(64, 64), 192>>>(x, t_cw2);
    tatt_kernel<<<64, 256>>>(t_w, t_b, t_v);
    xta_kernel<<<dim3(400, 64), 64>>>(x);

    // spatial attention
    tile64_kernel<1><<<dim3(7, 7, 64), 256>>>(nullptr, s_b, 400, 400, 64);
    tile64_kernel<0><<<dim3(7, 7, 1), 256>>>(supports, nullptr, 400, 400, 400);
    sv_mma_kernel<<<dim3(4, 4, 64), 256, CH_SMEM>>>(s_v);
    colmax_kernel<<<64, 512>>>();
    smax_kernel<<<dim3(400, 64), 256>>>();

    // cheby (HMMA) + projection (HMMA, k=0 folded)
    cheby_mma_kernel<<<dim3(12, 4, 128), 256, CH_SMEM>>>(supports);
    proj_mma_kernel<<<dim3(50, 64), 256, PJ_SMEM>>>(g_w, g_bv);

    // temporal conv + conv1 residual fused (HMMA) + LN partials
    tc_mma_kernel<<<dim3(50, 64), 256, PJ_SMEM>>>(x, tc_w, tc_b, conv1_w, conv1_b, out);
    stats_kernel<<<64, 256>>>();
    ln_kernel<<<153600, 256>>>(out, ln_g, ln_b);

    // emit S_coef / T_coef
    copyout_kernel<<<(SZ_S + SZ_T + 255) / 256, 256>>>(out, out_size);
}

// round 12
// speedup vs baseline: 1.7305x; 1.0136x over previous
#include <cuda_runtime.h>
#include <cuda_bf16.h>
#include <math.h>
#include <stddef.h>
#include <stdint.h>

// Problem dims: B=64, C=64, CO=64, N=400, L=24, K=3, KT=3
// x layout [b,c,n,l]: idx = ((b*64+c)*400+n)*24+l
#define SZ_X      39321600
#define SZ_S      10240000
#define SZ_T      36864
#define OFF_S     39321600
#define OFF_T     49561600
#define SZ_TOTAL  49598464

// ---------------- scratch ----------------
__device__ float g_xta[SZ_X];            // x_TAt [b,n,c,l]
__device__ float g_Y[64*2*400*64*24];    // cheby k=1,2: [b,k-1,q, c*24+l]
__device__ float g_sg[SZ_X];
__device__ float g_f1t[64*24*400];
__device__ float g_f2t[64*64*24];
__device__ float g_f2s[64*64*400];
__device__ float g_gs[64*400*64];
__device__ float g_lsig[64*400*400];
__device__ float g_lg2s[64*400*400];
__device__ float g_Sscr[SZ_S];
__device__ float g_T[64*24*24];
__device__ float g_adj2[400*400];
__device__ float g_cmaxs[64*400];
__device__ float g_psum[64*50];
__device__ float g_psq[64*50];
__device__ float g_mu[64];
__device__ float g_rstd[64];

// ---------------- fused features + gs ----------------
// per (b,n): f1t[b,l,n], f2s[b,c,n], f1row (smem), gs[b,n,c] = f1row @ s_w
__global__ __launch_bounds__(256) void featA_kernel(const float* __restrict__ x,
                                                    const float* __restrict__ tcw1,
                                                    const float* __restrict__ scw1,
                                                    const float* __restrict__ scw2,
                                                    const float* __restrict__ sw) {
    int n = blockIdx.x, b = blockIdx.y;
    __shared__ float xs[1536];
    __shared__ float sws[1536];
    __shared__ float c1[64], c2[64], c3[24], f1sh[24];
    int tid = threadIdx.x;
    const float* xb = x + (size_t)b * 614400;
    for (int i = tid; i < 1536; i += 256) {
        int c = i / 24, l = i % 24;
        xs[i] = xb[c * 9600 + n * 24 + l];
        sws[i] = sw[i];
    }
    if (tid < 64) c1[tid] = tcw1[tid];
    else if (tid < 128) c2[tid - 64] = scw1[tid - 64];
    else if (tid < 152) c3[tid - 128] = scw2[tid - 128];
    __syncthreads();
    if (tid < 24) {
        int l = tid;
        float a1 = 0.f, a2 = 0.f;
        for (int c = 0; c < 64; c++) {
            float xv = xs[c * 24 + l];
            a1 += c1[c] * xv;
            a2 += c2[c] * xv;
        }
        g_f1t[(b * 24 + l) * 400 + n] = a1;
        f1sh[l] = a2;
    } else if (tid >= 64 && tid < 128) {
        int c = tid - 64;
        float a = 0.f;
        for (int l = 0; l < 24; l++) a += c3[l] * xs[c * 24 + l];
        g_f2s[(b * 64 + c) * 400 + n] = a;
    }
    __syncthreads();
    if (tid < 64) {
        float a = 0.f;
        for (int l = 0; l < 24; l++) a += f1sh[l] * sws[l * 64 + tid];
        g_gs[(b * 400 + n) * 64 + tid] = a;
    }
}

// ---------------- f2t ----------------
__global__ __launch_bounds__(192) void f2t_kernel(const float* __restrict__ x,
                                                  const float* __restrict__ tcw2) {
    int c = blockIdx.x, b = blockIdx.y;
    __shared__ float red[192];
    int tid = threadIdx.x;
    int l = tid % 24, g = tid / 24;
    const float* xb = x + (size_t)b * 614400 + c * 9600;
    float a = 0.f;
    for (int n = g; n < 400; n += 8) a += tcw2[n] * xb[n * 24 + l];
    red[tid] = a;
    __syncthreads();
    if (tid < 24) {
        float s = 0.f;
        for (int gg = 0; gg < 8; gg++) s += red[gg * 24 + tid];
        g_f2t[(b * 64 + c) * 24 + tid] = s;
    }
}

// ---------------- temporal attention ----------------
__global__ __launch_bounds__(256) void tatt_kernel(const float* __restrict__ tw,
                                                   const float* __restrict__ tb,
                                                   const float* __restrict__ tv) {
    int b = blockIdx.x;
    __shared__ float f1tile[24 * 64], twtile[64 * 64], f2ts[64 * 24], gt[24 * 64];
    __shared__ float lg[576], lg2[576], cmax[24], rsum[24];
    int tid = threadIdx.x;
    for (int i = tid; i < 1536; i += 256) f2ts[i] = g_f2t[b * 1536 + i];

    int pg = tid >> 6;
    int c  = tid & 63;
    float acc[6] = {0.f, 0.f, 0.f, 0.f, 0.f, 0.f};
    for (int n0 = 0; n0 < 400; n0 += 64) {
        __syncthreads();
        for (int i = tid; i < 1536; i += 256) {
            int p = i >> 6, nn = i & 63;
            f1tile[i] = (n0 + nn < 400) ? g_f1t[(b * 24 + p) * 400 + n0 + nn] : 0.f;
        }
        for (int i = tid; i < 4096; i += 256) {
            int nn = i >> 6, cc = i & 63;
            twtile[i] = (n0 + nn < 400) ? tw[(n0 + nn) * 64 + cc] : 0.f;
        }
        __syncthreads();
        for (int nn = 0; nn < 64; nn++) {
            float wv = twtile[nn * 64 + c];
#pragma unroll
            for (int j = 0; j < 6; j++) acc[j] += f1tile[(pg * 6 + j) * 64 + nn] * wv;
        }
    }
    __syncthreads();
#pragma unroll
    for (int j = 0; j < 6; j++) gt[(pg * 6 + j) * 64 + c] = acc[j];
    __syncthreads();
    for (int i = tid; i < 576; i += 256) {
        int p = i / 24, l = i % 24;
        float s = tb[i];
        for (int cc = 0; cc < 64; cc++) s += gt[p * 64 + cc] * f2ts[cc * 24 + l];
        lg[i] = 1.f / (1.f + expf(-s));
    }
    __syncthreads();
    for (int i = tid; i < 576; i += 256) {
        int p = i / 24, l = i % 24;
        float s = 0.f;
        for (int q = 0; q < 24; q++) s += tv[p * 24 + q] * lg[q * 24 + l];
        lg2[i] = s;
    }
    __syncthreads();
    if (tid < 24) {
        float m = -1e30f;
        for (int p = 0; p < 24; p++) m = fmaxf(m, lg2[p * 24 + tid]);
        cmax[tid] = m;
    }
    __syncthreads();
    for (int i = tid; i < 576; i += 256) {
        int l = i % 24;
        lg[i] = expf(lg2[i] - cmax[l]);
    }
    __syncthreads();
    if (tid < 24) {
        float s = 0.f;
        for (int l = 0; l < 24; l++) s += lg[tid * 24 + l];
        rsum[tid] = s;
    }
    __syncthreads();
    for (int i = tid; i < 576; i += 256) {
        int p = i / 24;
        g_T[b * 576 + i] = lg[i] / rsum[p];
    }
}

// ---------------- x_TAt (float2-vectorized) ----------------
__global__ __launch_bounds__(64) void xta_kernel(const float* __restrict__ x) {
    int n = blockIdx.x, b = blockIdx.y;
    __shared__ float xs[1536], Ts[576];
    int tid = threadIdx.x;
    const float* xb = x + (size_t)b * 614400;
    // stage x (float4): row c is 24 consecutive floats = 6 float4
    for (int i = tid; i < 384; i += 64) {
        int c = i / 6, v = i % 6;
        ((float4*)xs)[i] = *(const float4*)(xb + (size_t)c * 9600 + n * 24 + v * 4);
    }
    for (int i = tid; i < 144; i += 64)
        ((float4*)Ts)[i] = *(const float4*)(g_T + b * 576 + i * 4);
    __syncthreads();
    int cg = (tid >> 2) * 4, qg = (tid & 3) * 6;
    float acc[4][6] = {};
#pragma unroll
    for (int l2 = 0; l2 < 12; l2++) {
        float2 tv2[6];
#pragma unroll
        for (int j = 0; j < 6; j++) tv2[j] = *(const float2*)&Ts[(qg + j) * 24 + l2 * 2];
#pragma unroll
        for (int i = 0; i < 4; i++) {
            float2 xv = *(const float2*)&xs[(cg + i) * 24 + l2 * 2];
#pragma unroll
            for (int j = 0; j < 6; j++)
                acc[i][j] += xv.x * tv2[j].x + xv.y * tv2[j].y;
        }
    }
    float* o = g_xta + ((size_t)(b * 400 + n)) * 1536;
#pragma unroll
    for (int i = 0; i < 4; i++)
#pragma unroll
        for (int j = 0; j < 6; j++) o[(cg + i) * 24 + qg + j] = acc[i][j];
}

// ---------------- generic 64x64-tile SGEMM ----------------
// MODE 0: g_adj2 = A @ A ; MODE 1: lsig = sigmoid(gs@f2s + s_b)
template <int MODE>
__global__ __launch_bounds__(256) void tile64_kernel(const float* __restrict__ Aext,
                                                     const float* __restrict__ biasext,
                                                     int M, int N, int Kd) {
    int zb = blockIdx.z;
    const float* A;
    const float* Bm;
    float* C;
    if (MODE == 0) { A = Aext; Bm = Aext; C = g_adj2; }
    else { A = g_gs + (size_t)zb * 25600; Bm = g_f2s + (size_t)zb * 25600; C = g_lsig + (size_t)zb * 160000; }

    int m0 = blockIdx.y * 64, n0 = blockIdx.x * 64;
    __shared__ float As[16][68], Bs[16][68];
    int tid = threadIdx.x;
    int tx = tid & 15, ty = tid >> 4;
    float acc[4][4] = {};
    for (int k0 = 0; k0 < Kd; k0 += 16) {
#pragma unroll
        for (int r = 0; r < 4; r++) {
            int lin = tid + 256 * r;
            int kk = lin & 15, m = lin >> 4;
            float v = 0.f;
            if (m0 + m < M && k0 + kk < Kd) v = A[(size_t)(m0 + m) * Kd + k0 + kk];
            As[kk][m] = v;
            int j = lin & 63, kk2 = lin >> 6;
            float v2 = 0.f;
            if (k0 + kk2 < Kd && n0 + j < N) v2 = Bm[(size_t)(k0 + kk2) * N + n0 + j];
            Bs[kk2][j] = v2;
        }
        __syncthreads();
#pragma unroll
        for (int kk = 0; kk < 16; kk++) {
            float a[4], bb[4];
#pragma unroll
            for (int i = 0; i < 4; i++) a[i] = As[kk][ty * 4 + i];
#pragma unroll
            for (int j = 0; j < 4; j++) bb[j] = Bs[kk][tx * 4 + j];
#pragma unroll
            for (int i = 0; i < 4; i++)
#pragma unroll
                for (int j = 0; j < 4; j++) acc[i][j] += a[i] * bb[j];
        }
        __syncthreads();
    }
#pragma unroll
    for (int i = 0; i < 4; i++) {
        int m = m0 + ty * 4 + i;
        if (m >= M) break;
#pragma unroll
        for (int j = 0; j < 4; j++) {
            int nn = n0 + tx * 4 + j;
            if (nn >= N) continue;
            float v = acc[i][j];
            if (MODE == 1) v = 1.f / (1.f + expf(-(v + biasext[(size_t)m * N + nn])));
            C[(size_t)m * N + nn] = v;
        }
    }
}

// ---------------- column max / softmax ----------------
__global__ __launch_bounds__(512) void colmax_kernel() {
    int b = blockIdx.x;
    int tid = threadIdx.x;
    if (tid < 400) {
        const float* base = g_lg2s + (size_t)b * 160000 + tid;
        float m = -1e30f;
        for (int p = 0; p < 400; p++) m = fmaxf(m, base[p * 400]);
        g_cmaxs[b * 400 + tid] = m;
    }
}

__global__ __launch_bounds__(256) void smax_kernel() {
    int p = blockIdx.x, b = blockIdx.y;
    int tid = threadIdx.x;
    __shared__ float red[256];
    const float* row = g_lg2s + (size_t)b * 160000 + p * 400;
    const float* cm = g_cmaxs + b * 400;
    float* orow = g_Sscr + (size_t)b * 160000 + p * 400;
    float s = 0.f;
    for (int n = tid; n < 400; n += 256) {
        float e = expf(row[n] - cm[n]);
        orow[n] = e;
        s += e;
    }
    red[tid] = s;
    __syncthreads();
    for (int st = 128; st > 0; st >>= 1) {
        if (tid < st) red[tid] += red[tid + st];
        __syncthreads();
    }
    float inv = 1.f / red[0];
    for (int n = tid; n < 400; n += 256) orow[n] *= inv;
}

// ---------------- HMMA helper ----------------
__device__ __forceinline__ void mma16816(float* d, const uint32_t* a, const uint32_t* b) {
    asm volatile(
        "mma.sync.aligned.m16n8k16.row.col.f32.bf16.bf16.f32 "
        "{%0,%1,%2,%3}, {%4,%5,%6,%7}, {%8,%9}, {%0,%1,%2,%3};"
        : "+f"(d[0]), "+f"(d[1]), "+f"(d[2]), "+f"(d[3])
        : "r"(a[0]), "r"(a[1]), "r"(a[2]), "r"(a[3]), "r"(b[0]), "r"(b[1]));
}

// ======================================================================
// cheby via warp-level mma.sync (HMMA bf16, fp32 accum, hi/lo compensation)
// ======================================================================
#define CH_LDK 72
#define CH_ASZ (128 * CH_LDK)
#define CH_SMEM (4 * CH_ASZ * 2)

__global__ __launch_bounds__(256) void cheby_mma_kernel(const float* __restrict__ adj) {
    extern __shared__ char chsm[];
    __nv_bfloat16* As_hi = (__nv_bfloat16*)chsm;
    __nv_bfloat16* As_lo = As_hi + CH_ASZ;
    __nv_bfloat16* Bs_hi = As_lo + CH_ASZ;
    __nv_bfloat16* Bs_lo = Bs_hi + CH_ASZ;

    int tid = threadIdx.x;
    int wid = tid >> 5, lane = tid & 31;
    int g = lane >> 2, tg = lane & 3;
    int b = blockIdx.z >> 1;
    int kvar = blockIdx.z & 1;
    int q0 = blockIdx.y * 128;
    int j0 = blockIdx.x * 128;
    const float* Sb = g_Sscr + (size_t)b * 160000;
    const float* Xb = g_xta + (size_t)b * 614400;
    int m_off = (wid >> 2) * 64;
    int n_off = (wid & 3) * 32;

    float acc[4][4][4];
#pragma unroll
    for (int im = 0; im < 4; im++)
#pragma unroll
        for (int in_ = 0; in_ < 4; in_++)
#pragma unroll
            for (int r = 0; r < 4; r++) acc[im][in_][r] = 0.f;

    for (int ch = 0; ch < 7; ch++) {
        int n0k = ch * 64;
#pragma unroll 4
        for (int i = 0; i < 32; i++) {
            int lin = tid + 256 * i;
            int kk = lin & 63, q = lin >> 6;
            int gq = q0 + q, gn = n0k + kk;
            float a = 0.f;
            if (gq < 400 && gn < 400) {
                float s = Sb[gq * 400 + gn];
                if (kvar == 0) a = s * adj[gq * 400 + gn];
                else a = s * (2.f * g_adj2[gq * 400 + gn] - (gq == gn ? 1.f : 0.f));
            }
            __nv_bfloat16 h = __float2bfloat16(a);
            __nv_bfloat16 l = __float2bfloat16(a - __bfloat162float(h));
            As_hi[q * CH_LDK + kk] = h;
            As_lo[q * CH_LDK + kk] = l;
        }
#pragma unroll 4
        for (int i = 0; i < 32; i++) {
            int lin = tid + 256 * i;
            int j = lin & 127, kk = lin >> 7;
            int gn = n0k + kk;
            float v = (gn < 400) ? Xb[(size_t)gn * 1536 + j0 + j] : 0.f;
            __nv_bfloat16 h = __float2bfloat16(v);
            __nv_bfloat16 l = __float2bfloat16(v - __bfloat162float(h));
            Bs_hi[j * CH_LDK + kk] = h;
            Bs_lo[j * CH_LDK + kk] = l;
        }
        __syncthreads();
#pragma unroll
        for (int ks = 0; ks < 4; ks++) {
            int kb = ks * 16;
            uint32_t ah[4][4], al[4][4], bh[4][2], bl[4][2];
#pragma unroll
            for (int im = 0; im < 4; im++) {
                int r0 = m_off + im * 16 + g;
                int cA = kb + tg * 2;
                ah[im][0] = *(const uint32_t*)&As_hi[r0 * CH_LDK + cA];
                ah[im][1] = *(const uint32_t*)&As_hi[(r0 + 8) * CH_LDK + cA];
                ah[im][2] = *(const uint32_t*)&As_hi[r0 * CH_LDK + cA + 8];
                ah[im][3] = *(const uint32_t*)&As_hi[(r0 + 8) * CH_LDK + cA + 8];
                al[im][0] = *(const uint32_t*)&As_lo[r0 * CH_LDK + cA];
                al[im][1] = *(const uint32_t*)&As_lo[(r0 + 8) * CH_LDK + cA];
                al[im][2] = *(const uint32_t*)&As_lo[r0 * CH_LDK + cA + 8];
                al[im][3] = *(const uint32_t*)&As_lo[(r0 + 8) * CH_LDK + cA + 8];
            }
#pragma unroll
            for (int in_ = 0; in_ < 4; in_++) {
                int col = n_off + in_ * 8 + g;
                int rB = kb + tg * 2;
                bh[in_][0] = *(const uint32_t*)&Bs_hi[col * CH_LDK + rB];
                bh[in_][1] = *(const uint32_t*)&Bs_hi[col * CH_LDK + rB + 8];
                bl[in_][0] = *(const uint32_t*)&Bs_lo[col * CH_LDK + rB];
                bl[in_][1] = *(const uint32_t*)&Bs_lo[col * CH_LDK + rB + 8];
            }
#pragma unroll
            for (int im = 0; im < 4; im++)
#pragma unroll
                for (int in_ = 0; in_ < 4; in_++) {
                    mma16816(acc[im][in_], ah[im], bh[in_]);
                    mma16816(acc[im][in_], ah[im], bl[in_]);
                    mma16816(acc[im][in_], al[im], bh[in_]);
                }
        }
        __syncthreads();
    }

    float* Yb = g_Y + (size_t)(b * 2 + kvar) * 614400;
#pragma unroll
    for (int im = 0; im < 4; im++) {
        int r0 = q0 + m_off + im * 16 + g;
#pragma unroll
        for (int in_ = 0; in_ < 4; in_++) {
            int col = j0 + n_off + in_ * 8 + tg * 2;
            if (r0 < 400) {
                float2 v = make_float2(acc[im][in_][0], acc[im][in_][1]);
                *(float2*)&Yb[(size_t)r0 * 1536 + col] = v;
            }
            if (r0 + 8 < 400) {
                float2 v = make_float2(acc[im][in_][2], acc[im][in_][3]);
                *(float2*)&Yb[(size_t)(r0 + 8) * 1536 + col] = v;
            }
        }
    }
}

// ======================================================================
// s_v @ lsig via HMMA: lg2s[b,p,n] = sum_q s_v[p,q]*lsig[b,q,n]
// M=N=K=400; grid (4 n-blk, 4 p-blk, 64 b); same structure as cheby.
// ======================================================================
__global__ __launch_bounds__(256) void sv_mma_kernel(const float* __restrict__ sv) {
    extern __shared__ char svsm[];
    __nv_bfloat16* As_hi = (__nv_bfloat16*)svsm;
    __nv_bfloat16* As_lo = As_hi + CH_ASZ;
    __nv_bfloat16* Bs_hi = As_lo + CH_ASZ;
    __nv_bfloat16* Bs_lo = Bs_hi + CH_ASZ;

    int tid = threadIdx.x;
    int wid = tid >> 5, lane = tid & 31;
    int g = lane >> 2, tg = lane & 3;
    int b = blockIdx.z;
    int p0 = blockIdx.y * 128;
    int j0 = blockIdx.x * 128;
    const float* Lb = g_lsig + (size_t)b * 160000;
    int m_off = (wid >> 2) * 64;
    int n_off = (wid & 3) * 32;

    float acc[4][4][4];
#pragma unroll
    for (int im = 0; im < 4; im++)
#pragma unroll
        for (int in_ = 0; in_ < 4; in_++)
#pragma unroll
            for (int r = 0; r < 4; r++) acc[im][in_][r] = 0.f;

    for (int ch = 0; ch < 7; ch++) {
        int n0k = ch * 64;
#pragma unroll 4
        for (int i = 0; i < 32; i++) {
            int lin = tid + 256 * i;
            int kk = lin & 63, p = lin >> 6;
            int gp = p0 + p, gq = n0k + kk;
            float a = 0.f;
            if (gp < 400 && gq < 400) a = sv[gp * 400 + gq];
            __nv_bfloat16 h = __float2bfloat16(a);
            __nv_bfloat16 l = __float2bfloat16(a - __bfloat162float(h));
            As_hi[p * CH_LDK + kk] = h;
            As_lo[p * CH_LDK + kk] = l;
        }
#pragma unroll 4
        for (int i = 0; i < 32; i++) {
            int lin = tid + 256 * i;
            int j = lin & 127, kk = lin >> 7;
            int gq = n0k + kk, gn = j0 + j;
            float v = (gq < 400 && gn < 400) ? Lb[(size_t)gq * 400 + gn] : 0.f;
            __nv_bfloat16 h = __float2bfloat16(v);
            __nv_bfloat16 l = __float2bfloat16(v - __bfloat162float(h));
            Bs_hi[j * CH_LDK + kk] = h;
            Bs_lo[j * CH_LDK + kk] = l;
        }
        __syncthreads();
#pragma unroll
        for (int ks = 0; ks < 4; ks++) {
            int kb = ks * 16;
            uint32_t ah[4][4], al[4][4], bh[4][2], bl[4][2];
#pragma unroll
            for (int im = 0; im < 4; im++) {
                int r0 = m_off + im * 16 + g;
                int cA = kb + tg * 2;
                ah[im][0] = *(const uint32_t*)&As_hi[r0 * CH_LDK + cA];
                ah[im][1] = *(const uint32_t*)&As_hi[(r0 + 8) * CH_LDK + cA];
                ah[im][2] = *(const uint32_t*)&As_hi[r0 * CH_LDK + cA + 8];
                ah[im][3] = *(const uint32_t*)&As_hi[(r0 + 8) * CH_LDK + cA + 8];
                al[im][0] = *(const uint32_t*)&As_lo[r0 * CH_LDK + cA];
                al[im][1] = *(const uint32_t*)&As_lo[(r0 + 8) * CH_LDK + cA];
                al[im][2] = *(const uint32_t*)&As_lo[r0 * CH_LDK + cA + 8];
                al[im][3] = *(const uint32_t*)&As_lo[(r0 + 8) * CH_LDK + cA + 8];
            }
#pragma unroll
            for (int in_ = 0; in_ < 4; in_++) {
                int col = n_off + in_ * 8 + g;
                int rB = kb + tg * 2;
                bh[in_][0] = *(const uint32_t*)&Bs_hi[col * CH_LDK + rB];
                bh[in_][1] = *(const uint32_t*)&Bs_hi[col * CH_LDK + rB + 8];
                bl[in_][0] = *(const uint32_t*)&Bs_lo[col * CH_LDK + rB];
                bl[in_][1] = *(const uint32_t*)&Bs_lo[col * CH_LDK + rB + 8];
            }
#pragma unroll
            for (int im = 0; im < 4; im++)
#pragma unroll
                for (int in_ = 0; in_ < 4; in_++) {
                    mma16816(acc[im][in_], ah[im], bh[in_]);
                    mma16816(acc[im][in_], ah[im], bl[in_]);
                    mma16816(acc[im][in_], al[im], bh[in_]);
                }
        }
        __syncthreads();
    }

    float* Cb = g_lg2s + (size_t)b * 160000;
#pragma unroll
    for (int im = 0; im < 4; im++) {
        int r0 = p0 + m_off + im * 16 + g;
#pragma unroll
        for (int in_ = 0; in_ < 4; in_++) {
            int col = j0 + n_off + in_ * 8 + tg * 2;
            if (col < 400) {
                if (r0 < 400)
                    *(float2*)&Cb[(size_t)r0 * 400 + col] =
                        make_float2(acc[im][in_][0], acc[im][in_][1]);
                if (r0 + 8 < 400)
                    *(float2*)&Cb[(size_t)(r0 + 8) * 400 + col] =
                        make_float2(acc[im][in_][2], acc[im][in_][3]);
            }
        }
    }
}

// ======================================================================
// proj via HMMA:  sg[b,o,q,l] = relu(W[64x192] @ Y[192x(q,l)] + gb[o])
// ======================================================================
#define PJ_LDA 66
#define PJ_ASZ (64 * PJ_LDA)     // 4224
#define PJ_BSZ (192 * PJ_LDA)    // 12672
#define PJ_SMEM ((2 * PJ_ASZ + 2 * PJ_BSZ) * 2)  // 67584 bytes

__global__ __launch_bounds__(256) void proj_mma_kernel(const float* __restrict__ gw,
                                                       const float* __restrict__ gb) {
    extern __shared__ char pjsm[];
    __nv_bfloat16* Ah = (__nv_bfloat16*)pjsm;
    __nv_bfloat16* Al = Ah + PJ_ASZ;
    __nv_bfloat16* Bh = Al + PJ_ASZ;
    __nv_bfloat16* Bl = Bh + PJ_BSZ;
    __shared__ float sqq[8];
    int tid = threadIdx.x;
    int wid = tid >> 5, lane = tid & 31;
    int g = lane >> 2, tg = lane & 3;
    int b = blockIdx.y, q0 = blockIdx.x * 8;
    if (tid < 8) sqq[tid] = g_Sscr[(size_t)b * 160000 + (size_t)(q0 + tid) * 401];
    __syncthreads();

    float acc[4][3][4];
#pragma unroll
    for (int mf = 0; mf < 4; mf++)
#pragma unroll
        for (int nf = 0; nf < 3; nf++)
#pragma unroll
            for (int r = 0; r < 4; r++) acc[mf][nf][r] = 0.f;

    for (int k = 0; k < 3; k++) {
        for (int i = tid; i < 4096; i += 256) {
            int o = i >> 6, c = i & 63;
            float v = gw[o * 192 + c * 3 + k];
            __nv_bfloat16 h = __float2bfloat16(v);
            Ah[o * PJ_LDA + c] = h;
            Al[o * PJ_LDA + c] = __float2bfloat16(v - __bfloat162float(h));
        }
#pragma unroll 4
        for (int i = 0; i < 48; i++) {
            int lin = tid + 256 * i;
            int q = lin / 1536;
            int rem = lin - q * 1536;
            int c = rem / 24, l = rem - c * 24;
            float v;
            if (k == 0)
                v = sqq[q] * g_xta[((size_t)(b * 400 + q0 + q)) * 1536 + c * 24 + l];
            else
                v = g_Y[((size_t)(b * 2 + (k - 1)) * 400 + q0 + q) * 1536 + c * 24 + l];
            __nv_bfloat16 h = __float2bfloat16(v);
            int col = q * 24 + l;
            Bh[col * PJ_LDA + c] = h;
            Bl[col * PJ_LDA + c] = __float2bfloat16(v - __bfloat162float(h));
        }
        __syncthreads();
#pragma unroll
        for (int ks = 0; ks < 4; ks++) {
            int kb = ks * 16;
            uint32_t ah[4][4], al[4][4], bh[3][2], bl[3][2];
#pragma unroll
            for (int mf = 0; mf < 4; mf++) {
                int r0 = mf * 16 + g;
                int cA = kb + tg * 2;
                ah[mf][0] = *(const uint32_t*)&Ah[r0 * PJ_LDA + cA];
                ah[mf][1] = *(const uint32_t*)&Ah[(r0 + 8) * PJ_LDA + cA];
                ah[mf][2] = *(const uint32_t*)&Ah[r0 * PJ_LDA + cA + 8];
                ah[mf][3] = *(const uint32_t*)&Ah[(r0 + 8) * PJ_LDA + cA + 8];
                al[mf][0] = *(const uint32_t*)&Al[r0 * PJ_LDA + cA];
                al[mf][1] = *(const uint32_t*)&Al[(r0 + 8) * PJ_LDA + cA];
                al[mf][2] = *(const uint32_t*)&Al[r0 * PJ_LDA + cA + 8];
                al[mf][3] = *(const uint32_t*)&Al[(r0 + 8) * PJ_LDA + cA + 8];
            }
#pragma unroll
            for (int nf = 0; nf < 3; nf++) {
                int col = wid * 24 + nf * 8 + g;
                int rB = kb + tg * 2;
                bh[nf][0] = *(const uint32_t*)&Bh[col * PJ_LDA + rB];
                bh[nf][1] = *(const uint32_t*)&Bh[col * PJ_LDA + rB + 8];
                bl[nf][0] = *(const uint32_t*)&Bl[col * PJ_LDA + rB];
                bl[nf][1] = *(const uint32_t*)&Bl[col * PJ_LDA + rB + 8];
            }
#pragma unroll
            for (int mf = 0; mf < 4; mf++)
#pragma unroll
                for (int nf = 0; nf < 3; nf++) {
                    mma16816(acc[mf][nf], ah[mf], bh[nf]);
                    mma16816(acc[mf][nf], ah[mf], bl[nf]);
                    mma16816(acc[mf][nf], al[mf], bh[nf]);
                }
        }
        __syncthreads();
    }

    int q = q0 + wid;
#pragma unroll
    for (int mf = 0; mf < 4; mf++) {
        int o0 = mf * 16 + g;
        float b0 = gb[o0], b1 = gb[o0 + 8];
#pragma unroll
        for (int nf = 0; nf < 3; nf++) {
            int l = nf * 8 + tg * 2;
            float2 v0 = make_float2(fmaxf(acc[mf][nf][0] + b0, 0.f),
                                    fmaxf(acc[mf][nf][1] + b0, 0.f));
            *(float2*)&g_sg[(size_t)(b * 64 + o0) * 9600 + q * 24 + l] = v0;
            float2 v1 = make_float2(fmaxf(acc[mf][nf][2] + b1, 0.f),
                                    fmaxf(acc[mf][nf][3] + b1, 0.f));
            *(float2*)&g_sg[(size_t)(b * 64 + o0 + 8) * 9600 + q * 24 + l] = v1;
        }
    }
}

// ======================================================================
// temporal conv + residual (conv1 fused as 4th K chunk) via HMMA
// ======================================================================
__global__ __launch_bounds__(256) void tc_mma_kernel(const float* __restrict__ x,
                                                     const float* __restrict__ tcw,
                                                     const float* __restrict__ tcb,
                                                     const float* __restrict__ c1w,
                                                     const float* __restrict__ c1b,
                                                     float* __restrict__ hout) {
    extern __shared__ char tcsm[];
    __nv_bfloat16* Ah = (__nv_bfloat16*)tcsm;
    __nv_bfloat16* Al = Ah + PJ_ASZ;
    __nv_bfloat16* Bh = Al + PJ_ASZ;
    __nv_bfloat16* Bl = Bh + PJ_BSZ;
    __shared__ float r1[256], r2[256];
    int tid = threadIdx.x;
    int wid = tid >> 5, lane = tid & 31;
    int g = lane >> 2, tg = lane & 3;
    int b = blockIdx.y, n0 = blockIdx.x * 8;

    float acc[4][3][4];
#pragma unroll
    for (int mf = 0; mf < 4; mf++)
#pragma unroll
        for (int nf = 0; nf < 3; nf++)
#pragma unroll
            for (int r = 0; r < 4; r++) acc[mf][nf][r] = 0.f;

    for (int kc = 0; kc < 4; kc++) {
        for (int i = tid; i < 4096; i += 256) {
            int o = i >> 6, c = i & 63;
            float v = (kc < 3) ? tcw[o * 192 + c * 3 + kc] : c1w[o * 64 + c];
            __nv_bfloat16 h = __float2bfloat16(v);
            Ah[o * PJ_LDA + c] = h;
            Al[o * PJ_LDA + c] = __float2bfloat16(v - __bfloat162float(h));
        }
#pragma unroll 4
        for (int i = 0; i < 48; i++) {
            int lin = tid + 256 * i;
            int q = lin / 1536;
            int rem = lin - q * 1536;
            int c = rem / 24, l = rem - c * 24;
            float v;
            if (kc < 3) {
                int ls = l + kc - 1;
                v = (ls >= 0 && ls < 24)
                        ? g_sg[(size_t)(b * 64 + c) * 9600 + (n0 + q) * 24 + ls]
                        : 0.f;
            } else {
                v = x[((size_t)(b * 64 + c) * 400 + n0 + q) * 24 + l];
            }
            __nv_bfloat16 h = __float2bfloat16(v);
            int col = q * 24 + l;
            Bh[col * PJ_LDA + c] = h;
            Bl[col * PJ_LDA + c] = __float2bfloat16(v - __bfloat162float(h));
        }
        __syncthreads();
#pragma unroll
        for (int ks = 0; ks < 4; ks++) {
            int kb = ks * 16;
            uint32_t ah[4][4], al[4][4], bh[3][2], bl[3][2];
#pragma unroll
            for (int mf = 0; mf < 4; mf++) {
                int r0 = mf * 16 + g;
                int cA = kb + tg * 2;
                ah[mf][0] = *(const uint32_t*)&Ah[r0 * PJ_LDA + cA];
                ah[mf][1] = *(const uint32_t*)&Ah[(r0 + 8) * PJ_LDA + cA];
                ah[mf][2] = *(const uint32_t*)&Ah[r0 * PJ_LDA + cA + 8];
                ah[mf][3] = *(const uint32_t*)&Ah[(r0 + 8) * PJ_LDA + cA + 8];
                al[mf][0] = *(const uint32_t*)&Al[r0 * PJ_LDA + cA];
                al[mf][1] = *(const uint32_t*)&Al[(r0 + 8) * PJ_LDA + cA];
                al[mf][2] = *(const uint32_t*)&Al[r0 * PJ_LDA + cA + 8];
                al[mf][3] = *(const uint32_t*)&Al[(r0 + 8) * PJ_LDA + cA + 8];
            }
#pragma unroll
            for (int nf = 0; nf < 3; nf++) {
                int col = wid * 24 + nf * 8 + g;
                int rB = kb + tg * 2;
                bh[nf][0] = *(const uint32_t*)&Bh[col * PJ_LDA + rB];
                bh[nf][1] = *(const uint32_t*)&Bh[col * PJ_LDA + rB + 8];
                bl[nf][0] = *(const uint32_t*)&Bl[col * PJ_LDA + rB];
                bl[nf][1] = *(const uint32_t*)&Bl[col * PJ_LDA + rB + 8];
            }
#pragma unroll
            for (int mf = 0; mf < 4; mf++)
#pragma unroll
                for (int nf = 0; nf < 3; nf++) {
                    mma16816(acc[mf][nf], ah[mf], bh[nf]);
                    mma16816(acc[mf][nf], ah[mf], bl[nf]);
                    mma16816(acc[mf][nf], al[mf], bh[nf]);
                }
        }
        __syncthreads();
    }

    int n = n0 + wid;
    float s = 0.f, ss = 0.f;
#pragma unroll
    for (int mf = 0; mf < 4; mf++) {
        int o0 = mf * 16 + g;
        float b0 = tcb[o0] + c1b[o0];
        float b1 = tcb[o0 + 8] + c1b[o0 + 8];
#pragma unroll
        for (int nf = 0; nf < 3; nf++) {
            int l = nf * 8 + tg * 2;
            float h0 = fmaxf(acc[mf][nf][0] + b0, 0.f);
            float h1 = fmaxf(acc[mf][nf][1] + b0, 0.f);
            float h2 = fmaxf(acc[mf][nf][2] + b1, 0.f);
            float h3 = fmaxf(acc[mf][nf][3] + b1, 0.f);
            *(float2*)&hout[(size_t)(b * 64 + o0) * 9600 + n * 24 + l] = make_float2(h0, h1);
            *(float2*)&hout[(size_t)(b * 64 + o0 + 8) * 9600 + n * 24 + l] = make_float2(h2, h3);
            s += h0 + h1 + h2 + h3;
            ss += h0 * h0 + h1 * h1 + h2 * h2 + h3 * h3;
        }
    }
    r1[tid] = s; r2[tid] = ss;
    __syncthreads();
    for (int st = 128; st > 0; st >>= 1) {
        if (tid < st) { r1[tid] += r1[tid + st]; r2[tid] += r2[tid + st]; }
        __syncthreads();
    }
    if (tid == 0) {
        g_psum[b * 50 + blockIdx.x] = r1[0];
        g_psq[b * 50 + blockIdx.x] = r2[0];
    }
}

// ---------------- per-batch stats ----------------
__global__ __launch_bounds__(256) void stats_kernel() {
    int b = blockIdx.x;
    int tid = threadIdx.x;
    __shared__ double d1[256], d2[256];
    double s = 0.0, ss = 0.0;
    for (int i = tid; i < 50; i += 256) { s += (double)g_psum[b * 50 + i]; ss += (double)g_psq[b * 50 + i]; }
    d1[tid] = s; d2[tid] = ss;
    __syncthreads();
    for (int st = 128; st > 0; st >>= 1) {
        if (tid < st) { d1[tid] += d1[tid + st]; d2[tid] += d2[tid + st]; }
        __syncthreads();
    }
    if (tid == 0) {
        double mu = d1[0] / 614400.0;
        double var = d2[0] / 614400.0 - mu * mu;
        g_mu[b] = (float)mu;
        g_rstd[b] = (float)(1.0 / sqrt(var + 1e-5));
    }
}

// ---------------- final layernorm ----------------
__global__ __launch_bounds__(256) void ln_kernel(float* __restrict__ out,
                                                 const float* __restrict__ lng,
                                                 const float* __restrict__ lnb) {
    size_t idx = (size_t)blockIdx.x * 256 + threadIdx.x;
    if (idx >= (size_t)SZ_X) return;
    int b = (int)(idx / 614400);
    int r = (int)(idx % 614400);
    out[idx] = (out[idx] - g_mu[b]) * g_rstd[b] * lng[r] + lnb[r];
}

// ---------------- copy S_coef / T_coef ----------------
__global__ __launch_bounds__(256) void copyout_kernel(float* __restrict__ out, int out_size) {
    if (out_size < SZ_TOTAL) return;
    size_t idx = (size_t)blockIdx.x * 256 + threadIdx.x;
    if (idx < (size_t)SZ_S) {
        out[OFF_S + idx] = g_Sscr[idx];
    } else if (idx < (size_t)(SZ_S + SZ_T)) {
        size_t t = idx - SZ_S;
        int b = (int)(t / 576);
        int rem = (int)(t % 576);
        int l = rem / 24, p = rem % 24;
        out[OFF_T + t] = g_T[b * 576 + p * 24 + l];
    }
}

// ---------------- launch ----------------
extern "C" void kernel_launch(void* const* d_in, const int* in_sizes, int n_in,
                              void* d_out, int out_size) {
    const float* x        = (const float*)d_in[0];
    const float* supports = (const float*)d_in[1];
    const float* conv1_w  = (const float*)d_in[2];
    const float* conv1_b  = (const float*)d_in[3];
    const float* t_cw1    = (const float*)d_in[4];
    const float* t_cw2    = (const float*)d_in[5];
    const float* t_w      = (const float*)d_in[6];
    const float* t_b      = (const float*)d_in[7];
    const float* t_v      = (const float*)d_in[8];
    const float* s_cw1    = (const float*)d_in[9];
    const float* s_cw2    = (const float*)d_in[10];
    const float* s_w      = (const float*)d_in[11];
    const float* s_b      = (const float*)d_in[12];
    const float* s_v      = (const float*)d_in[13];
    const float* g_w      = (const float*)d_in[14];
    const float* g_bv     = (const float*)d_in[15];
    const float* tc_w     = (const float*)d_in[16];
    const float* tc_b     = (const float*)d_in[17];
    const float* ln_g     = (const float*)d_in[18];
    const float* ln_b     = (const float*)d_in[19];
    float* out = (float*)d_out;

    cudaFuncSetAttribute(cheby_mma_kernel, cudaFuncAttributeMaxDynamicSharedMemorySize, CH_SMEM);
    cudaFuncSetAttribute(sv_mma_kernel, cudaFuncAttributeMaxDynamicSharedMemorySize, CH_SMEM);
    cudaFuncSetAttribute(proj_mma_kernel, cudaFuncAttributeMaxDynamicSharedMemorySize, PJ_SMEM);
    cudaFuncSetAttribute(tc_mma_kernel, cudaFuncAttributeMaxDynamicSharedMemorySize, PJ_SMEM);

    // independent front-end passes (gs fused into featA)
    featA_kernel<<<dim3(400, 64), 256>>>(x, t_cw1, s_cw1, s_cw2, s_w);
    f2t_kernel<<<dim3(64, 64), 192>>>(x, t_cw2);
    tatt_kernel<<<64, 256>>>(t_w, t_b, t_v);
    xta_kernel<<<dim3(400, 64), 64>>>(x);

    // spatial attention
    tile64_kernel<1><<<dim3(7, 7, 64), 256>>>(nullptr, s_b, 400, 400, 64);
    tile64_kernel<0><<<dim3(7, 7, 1), 256>>>(supports, nullptr, 400, 400, 400);
    sv_mma_kernel<<<dim3(4, 4, 64), 256, CH_SMEM>>>(s_v);
    colmax_kernel<<<64, 512>>>();
    smax_kernel<<<dim3(400, 64), 256>>>();

    // cheby (HMMA) + projection (HMMA, k=0 folded)
    cheby_mma_kernel<<<dim3(12, 4, 128), 256, CH_SMEM>>>(supports);
    proj_mma_kernel<<<dim3(50, 64), 256, PJ_SMEM>>>(g_w, g_bv);

    // temporal conv + conv1 residual fused (HMMA) + LN partials
    tc_mma_kernel<<<dim3(50, 64), 256, PJ_SMEM>>>(x, tc_w, tc_b, conv1_w, conv1_b, out);
    stats_kernel<<<64, 256>>>();
    ln_kernel<<<153600, 256>>>(out, ln_g, ln_b);

    // emit S_coef / T_coef
    copyout_kernel<<<(SZ_S + SZ_T + 255) / 256, 256>>>(out, out_size);
}